// round 1
// baseline (speedup 1.0000x reference)
#include <cuda_runtime.h>
#include <cuda_bf16.h>

// Problem constants (fixed by the reference setup)
#define N_NODES 50000
#define DEG     16
#define IN_F    256
#define HEADS   4
#define OUT_F   64
#define HF      256          // HEADS * OUT_F
#define NEG_SLOPE 0.2f

// Scratch (allocation-free rule: __device__ globals)
__device__ float g_h [N_NODES * HF];       // projected features, 51.2 MB
__device__ float g_ai[N_NODES * HEADS];    // destination attention halves
__device__ float g_aj[N_NODES * HEADS];    // source attention halves

// ---------------------------------------------------------------------------
// Kernel 1: h = x @ W^T   (M=50000, N=256, K=256, fp32)
// 64x64 block tile, 256 threads, 4x4 per thread, K-tile 32.
// ---------------------------------------------------------------------------
#define BM 64
#define BN 64
#define BK 32

__global__ void __launch_bounds__(256) gemm_kernel(const float* __restrict__ x,
                                                   const float* __restrict__ W)
{
    __shared__ float As[BK][BM + 1];   // padded: conflict-free transposed store
    __shared__ float Bs[BK][BN + 1];

    const int tid = threadIdx.x;
    const int bm  = blockIdx.y * BM;
    const int bn  = blockIdx.x * BN;   // bn in {0,64,128,192}, always in-bounds for W
    const int tx  = tid & 15;          // 16 thread cols
    const int ty  = tid >> 4;          // 16 thread rows

    float acc[4][4];
#pragma unroll
    for (int i = 0; i < 4; i++)
#pragma unroll
        for (int j = 0; j < 4; j++) acc[i][j] = 0.f;

    for (int k0 = 0; k0 < IN_F; k0 += BK) {
        // Load A (64 rows x 32 k) and B (64 W-rows x 32 k), transposed into SMEM.
        // idx = tid + i*256 over 2048 elems; warp reads one 128B row segment.
#pragma unroll
        for (int i = 0; i < 8; i++) {
            int idx = tid + i * 256;
            int r   = idx >> 5;        // 0..63
            int kk  = idx & 31;        // 0..31
            int row = bm + r;
            As[kk][r] = (row < N_NODES) ? x[row * IN_F + k0 + kk] : 0.f;
            Bs[kk][r] = W[(bn + r) * IN_F + k0 + kk];
        }
        __syncthreads();

#pragma unroll
        for (int kk = 0; kk < BK; kk++) {
            float a[4], b[4];
#pragma unroll
            for (int i = 0; i < 4; i++) a[i] = As[kk][ty * 4 + i];
#pragma unroll
            for (int j = 0; j < 4; j++) b[j] = Bs[kk][tx * 4 + j];
#pragma unroll
            for (int i = 0; i < 4; i++)
#pragma unroll
                for (int j = 0; j < 4; j++) acc[i][j] += a[i] * b[j];
        }
        __syncthreads();
    }

#pragma unroll
    for (int i = 0; i < 4; i++) {
        int row = bm + ty * 4 + i;
        if (row < N_NODES) {
            float* dst = &g_h[row * HF + bn + tx * 4];
#pragma unroll
            for (int j = 0; j < 4; j++) dst[j] = acc[i][j];
        }
    }
}

// ---------------------------------------------------------------------------
// Kernel 2: a_i[n,h] = <h[n,h,:], att_i[h,:]>, same for a_j. One warp / node.
// Lane L owns features [8L, 8L+8); head = L/8; reduce within 8-lane groups.
// ---------------------------------------------------------------------------
__global__ void __launch_bounds__(256) attvec_kernel(const float* __restrict__ att_i,
                                                     const float* __restrict__ att_j)
{
    int warp = (blockIdx.x * blockDim.x + threadIdx.x) >> 5;
    int lane = threadIdx.x & 31;
    if (warp >= N_NODES) return;

    const float4* hv = (const float4*)(g_h + warp * HF);
    float4 v0 = hv[lane * 2];
    float4 v1 = hv[lane * 2 + 1];

    const float4* ai = (const float4*)att_i;  // 256 floats, [H,F] flattened
    const float4* aj = (const float4*)att_j;
    float4 i0 = ai[lane * 2], i1 = ai[lane * 2 + 1];
    float4 j0 = aj[lane * 2], j1 = aj[lane * 2 + 1];

    float si = v0.x*i0.x + v0.y*i0.y + v0.z*i0.z + v0.w*i0.w
             + v1.x*i1.x + v1.y*i1.y + v1.z*i1.z + v1.w*i1.w;
    float sj = v0.x*j0.x + v0.y*j0.y + v0.z*j0.z + v0.w*j0.w
             + v1.x*j1.x + v1.y*j1.y + v1.z*j1.z + v1.w*j1.w;

#pragma unroll
    for (int off = 4; off >= 1; off >>= 1) {
        si += __shfl_xor_sync(0xffffffffu, si, off);
        sj += __shfl_xor_sync(0xffffffffu, sj, off);
    }
    if ((lane & 7) == 0) {
        int head = lane >> 3;
        g_ai[warp * HEADS + head] = si;
        g_aj[warp * HEADS + head] = sj;
    }
}

// ---------------------------------------------------------------------------
// Kernel 3: per-edge logits -> segment softmax -> weighted aggregate.
// 4 nodes per 256-thread block; 64 threads per node; float4 coalesced gather.
// col_id dtype (int32 vs int64) sniffed at runtime: int64 high words are 0.
// ---------------------------------------------------------------------------
__global__ void __launch_bounds__(256) gat_kernel(const int* __restrict__ col32,
                                                  float* __restrict__ out)
{
    __shared__ int   s_src[4][DEG];
    __shared__ float s_alpha[4][HEADS][DEG];
    __shared__ int   s_is64;

    const int tid = threadIdx.x;
    if (tid == 0) {
        // values < 50000 and nonnegative: int64 => odd 32-bit words are all 0
        s_is64 = ((col32[1] | col32[3] | col32[5]) == 0) ? 1 : 0;
    }
    __syncthreads();

    const int g    = tid >> 6;          // node group within block, 0..3
    const int t    = tid & 63;          // thread within group
    const int node = blockIdx.x * 4 + g;
    const int is64 = s_is64;

    // 1) gather edge sources
    if (t < DEG) {
        int e = node * DEG + t;
        s_src[g][t] = is64 ? col32[2 * e] : col32[e];
    }
    __syncthreads();

    // 2) per-edge logits with leaky relu (64 threads = 16 edges x 4 heads)
    {
        int e  = t >> 2;
        int hh = t & 3;
        int src = s_src[g][e];
        float v = g_ai[node * HEADS + hh] + g_aj[src * HEADS + hh];
        v = (v > 0.f) ? v : v * NEG_SLOPE;
        s_alpha[g][hh][e] = v;
    }
    __syncthreads();

    // 3) stable softmax per (node, head): 4 threads each handle one head
    if (t < HEADS) {
        int hh = t;
        float m = -3.402823466e+38f;
#pragma unroll
        for (int e = 0; e < DEG; e++) m = fmaxf(m, s_alpha[g][hh][e]);
        float p[DEG];
        float s = 0.f;
#pragma unroll
        for (int e = 0; e < DEG; e++) { p[e] = expf(s_alpha[g][hh][e] - m); s += p[e]; }
        float inv = 1.f / (s + 1e-16f);
#pragma unroll
        for (int e = 0; e < DEG; e++) s_alpha[g][hh][e] = p[e] * inv;
    }
    __syncthreads();

    // 4) weighted aggregate: thread t owns features [4t, 4t+4); head = t/16
    const int hh = t >> 4;
    float4 acc = make_float4(0.f, 0.f, 0.f, 0.f);
#pragma unroll
    for (int e = 0; e < DEG; e++) {
        float a = s_alpha[g][hh][e];
        const float4* hv = (const float4*)(g_h + s_src[g][e] * HF);
        float4 v = hv[t];
        acc.x += a * v.x;  acc.y += a * v.y;
        acc.z += a * v.z;  acc.w += a * v.w;
    }
    ((float4*)out)[node * (HF / 4) + t] = acc;
}

// ---------------------------------------------------------------------------
// Launch: inputs in metadata order:
//   0: x [N,256] f32   1: row_id (unused)   2: row_ptr (unused)
//   3: col_id [E]      4: W [256,256] f32   5: att_i [1,4,64]   6: att_j [1,4,64]
// ---------------------------------------------------------------------------
extern "C" void kernel_launch(void* const* d_in, const int* in_sizes, int n_in,
                              void* d_out, int out_size)
{
    const float* x     = (const float*)d_in[0];
    const int*   col   = (const int*)  d_in[3];
    const float* W     = (const float*)d_in[4];
    const float* att_i = (const float*)d_in[5];
    const float* att_j = (const float*)d_in[6];
    float*       out   = (float*)d_out;

    dim3 ggrid(HF / BN, (N_NODES + BM - 1) / BM);   // (4, 782)
    gemm_kernel<<<ggrid, 256>>>(x, W);

    attvec_kernel<<<(N_NODES * 32 + 255) / 256, 256>>>(att_i, att_j);

    gat_kernel<<<N_NODES / 4, 256>>>(col, out);
}

// round 3
// speedup vs baseline: 1.7891x; 1.7891x over previous
#include <cuda_runtime.h>
#include <cuda_bf16.h>
#include <cstdint>

// Problem constants (fixed by the reference setup)
#define N_NODES 50000
#define DEG     16
#define IN_F    256
#define HEADS   4
#define OUT_F   64
#define HF      256          // HEADS * OUT_F
#define NEG_SLOPE 0.2f

// Scratch (allocation-free rule: __device__ globals)
__device__ float g_h [N_NODES * HF];       // projected features, 51.2 MB
__device__ float g_ai[N_NODES * HEADS];    // destination attention halves
__device__ float g_aj[N_NODES * HEADS];    // source attention halves

// ===========================================================================
// GEMM: g_h = x @ W^T  (M=50048 padded, N=256, K=256) via mma.sync bf16
// with hi/lo split for fp32-level accuracy (hi*hi + lo*hi + hi*lo).
// CTA tile 128x128, 8 warps (4 M x 2 N), warp tile 32x64, K staged by 64.
// Fused epilogue computes g_ai / g_aj (each warp's 64 cols = one head).
// ===========================================================================
#define GT       256          // threads per CTA
#define STRB     72           // smem row stride in bf16 (64 + 8 pad) = 144 B
#define TILE_BYTES (128 * STRB * 2)          // 18432 B per matrix
#define OFF_AHI  0
#define OFF_ALO  (TILE_BYTES)
#define OFF_BHI  (2 * TILE_BYTES)
#define OFF_BLO  (3 * TILE_BYTES)
#define GEMM_SMEM (4 * TILE_BYTES)           // 73728 B

__device__ __forceinline__ uint32_t smem_to_u32(const void* p) {
    uint32_t a;
    asm("{ .reg .u64 t; cvta.to.shared.u64 t, %1; cvt.u32.u64 %0, t; }"
        : "=r"(a) : "l"(p));
    return a;
}

__device__ __forceinline__ void ldsm4(uint32_t* r, uint32_t addr) {
    asm volatile("ldmatrix.sync.aligned.m8n8.x4.shared.b16 {%0,%1,%2,%3}, [%4];"
                 : "=r"(r[0]), "=r"(r[1]), "=r"(r[2]), "=r"(r[3]) : "r"(addr));
}

__device__ __forceinline__ void mma_bf16(float* d, const uint32_t* a,
                                         uint32_t b0, uint32_t b1) {
    asm volatile("mma.sync.aligned.m16n8k16.row.col.f32.bf16.bf16.f32 "
                 "{%0,%1,%2,%3}, {%4,%5,%6,%7}, {%8,%9}, {%0,%1,%2,%3};"
                 : "+f"(d[0]), "+f"(d[1]), "+f"(d[2]), "+f"(d[3])
                 : "r"(a[0]), "r"(a[1]), "r"(a[2]), "r"(a[3]), "r"(b0), "r"(b1));
}

__device__ __forceinline__ uint32_t pack_bf2(__nv_bfloat16 a, __nv_bfloat16 b) {
    __nv_bfloat162 t; t.x = a; t.y = b;
    return *reinterpret_cast<uint32_t*>(&t);
}

// split float4 into hi (bf16x4) and lo (bf16x4) packed words
__device__ __forceinline__ void split4(float4 v, uint2& hi, uint2& lo) {
    __nv_bfloat16 hx = __float2bfloat16(v.x), hy = __float2bfloat16(v.y);
    __nv_bfloat16 hz = __float2bfloat16(v.z), hw = __float2bfloat16(v.w);
    hi.x = pack_bf2(hx, hy);
    hi.y = pack_bf2(hz, hw);
    lo.x = pack_bf2(__float2bfloat16(v.x - __bfloat162float(hx)),
                    __float2bfloat16(v.y - __bfloat162float(hy)));
    lo.y = pack_bf2(__float2bfloat16(v.z - __bfloat162float(hz)),
                    __float2bfloat16(v.w - __bfloat162float(hw)));
}

extern __shared__ char g_smem[];

__global__ void __launch_bounds__(GT)
gemm_mma_kernel(const float* __restrict__ x, const float* __restrict__ W,
                const float* __restrict__ att_i, const float* __restrict__ att_j)
{
    const int tid  = threadIdx.x;
    const int wid  = tid >> 5;
    const int lane = tid & 31;
    const int wm   = wid >> 1;          // 0..3 (M dim)
    const int wn   = wid & 1;           // 0..1 (N dim)
    const int bx   = blockIdx.x;        // N block (0,1)
    const int m0   = blockIdx.y * 128;

    const uint32_t sb  = smem_to_u32(g_smem);
    const uint32_t aHI = sb + OFF_AHI, aLO = sb + OFF_ALO;
    const uint32_t bHI = sb + OFF_BHI, bLO = sb + OFF_BLO;

    float acc[2][8][4] = {};            // [m-tile][n-tile][frag]

    for (int s = 0; s < 4; s++) {
        const int k0 = s * 64;
        if (s) __syncthreads();

        // ---- stage A (128 rows x 64 k) and B (128 n x 64 k), split hi/lo ----
#pragma unroll
        for (int i = 0; i < 8; i++) {
            int idx = tid + i * GT;             // 0..2047
            int row = idx >> 4;
            int c4  = (idx & 15) * 4;
            // A
            int grow = m0 + row;
            float4 va = (grow < N_NODES)
                ? *reinterpret_cast<const float4*>(x + (size_t)grow * IN_F + k0 + c4)
                : make_float4(0.f, 0.f, 0.f, 0.f);
            uint2 hi, lo;
            split4(va, hi, lo);
            uint32_t off = (uint32_t)row * (STRB * 2) + (uint32_t)c4 * 2;
            *reinterpret_cast<uint2*>(g_smem + OFF_AHI + off) = hi;
            *reinterpret_cast<uint2*>(g_smem + OFF_ALO + off) = lo;
            // B (W rows bx*128 + row, always in-bounds)
            float4 vb = *reinterpret_cast<const float4*>(
                W + (size_t)(bx * 128 + row) * IN_F + k0 + c4);
            split4(vb, hi, lo);
            *reinterpret_cast<uint2*>(g_smem + OFF_BHI + off) = hi;
            *reinterpret_cast<uint2*>(g_smem + OFF_BLO + off) = lo;
        }
        __syncthreads();

        // ---- compute: 4 k16 steps ----
#pragma unroll
        for (int ks = 0; ks < 4; ks++) {
            const uint32_t kb = (uint32_t)ks * 32;   // byte offset of k16 step

            // A fragments: rows wm*32 + mt*16 + (lane&15), k half via lane>>4
            uint32_t aoff = (uint32_t)(wm * 32 + (lane & 15)) * (STRB * 2)
                          + kb + ((lane >> 4) << 4);
            uint32_t Ah0[4], Ah1[4], Al0[4], Al1[4];
            ldsm4(Ah0, aHI + aoff);
            ldsm4(Ah1, aHI + aoff + 16 * (STRB * 2));
            ldsm4(Al0, aLO + aoff);
            ldsm4(Al1, aLO + aoff + 16 * (STRB * 2));

            // B base: n row within CTA, two n-tiles per ldsm4
            uint32_t nrow = (uint32_t)(wn * 64) + (lane & 7) + ((lane >> 4) << 3);
            uint32_t khalf = (lane >> 3) & 1;
            uint32_t bbase = nrow * (STRB * 2) + kb + khalf * 16;
#pragma unroll
            for (int p = 0; p < 4; p++) {
                uint32_t boff = bbase + (uint32_t)p * 16 * (STRB * 2);
                uint32_t Bh[4], Bl[4];
                ldsm4(Bh, bHI + boff);
                ldsm4(Bl, bLO + boff);
#pragma unroll
                for (int h = 0; h < 2; h++) {
                    const int nt = p * 2 + h;
                    uint32_t bh0 = Bh[h * 2], bh1 = Bh[h * 2 + 1];
                    uint32_t bl0 = Bl[h * 2], bl1 = Bl[h * 2 + 1];
                    mma_bf16(acc[0][nt], Ah0, bh0, bh1);
                    mma_bf16(acc[1][nt], Ah1, bh0, bh1);
                    mma_bf16(acc[0][nt], Al0, bh0, bh1);
                    mma_bf16(acc[1][nt], Al1, bh0, bh1);
                    mma_bf16(acc[0][nt], Ah0, bl0, bl1);
                    mma_bf16(acc[1][nt], Ah1, bl0, bl1);
                }
            }
        }
    }

    // ---- epilogue: write g_h + fused attention dots ----
    const int head    = bx * 2 + wn;           // this warp's head
    const int colbase = bx * 128 + wn * 64;
    const int rbase   = m0 + wm * 32 + (lane >> 2);
    float si[2][2] = {}, sj[2][2] = {};

#pragma unroll
    for (int nt = 0; nt < 8; nt++) {
        const int g = colbase + nt * 8 + (lane & 3) * 2;
        const float ai0 = att_i[g], ai1 = att_i[g + 1];
        const float aj0 = att_j[g], aj1 = att_j[g + 1];
#pragma unroll
        for (int mt = 0; mt < 2; mt++) {
            si[mt][0] += acc[mt][nt][0] * ai0 + acc[mt][nt][1] * ai1;
            sj[mt][0] += acc[mt][nt][0] * aj0 + acc[mt][nt][1] * aj1;
            si[mt][1] += acc[mt][nt][2] * ai0 + acc[mt][nt][3] * ai1;
            sj[mt][1] += acc[mt][nt][2] * aj0 + acc[mt][nt][3] * aj1;
            const int r0 = rbase + mt * 16;
            if (r0 < N_NODES)
                *reinterpret_cast<float2*>(g_h + (size_t)r0 * HF + g)
                    = make_float2(acc[mt][nt][0], acc[mt][nt][1]);
            const int r1 = r0 + 8;
            if (r1 < N_NODES)
                *reinterpret_cast<float2*>(g_h + (size_t)r1 * HF + g)
                    = make_float2(acc[mt][nt][2], acc[mt][nt][3]);
        }
    }
    // reduce across the 4 lanes sharing each row
#pragma unroll
    for (int off = 1; off <= 2; off <<= 1) {
#pragma unroll
        for (int mt = 0; mt < 2; mt++)
#pragma unroll
            for (int hf = 0; hf < 2; hf++) {
                si[mt][hf] += __shfl_xor_sync(0xffffffffu, si[mt][hf], off);
                sj[mt][hf] += __shfl_xor_sync(0xffffffffu, sj[mt][hf], off);
            }
    }
    if ((lane & 3) == 0) {
#pragma unroll
        for (int mt = 0; mt < 2; mt++)
#pragma unroll
            for (int hf = 0; hf < 2; hf++) {
                const int r = rbase + mt * 16 + hf * 8;
                if (r < N_NODES) {
                    g_ai[(size_t)r * HEADS + head] = si[mt][hf];
                    g_aj[(size_t)r * HEADS + head] = sj[mt][hf];
                }
            }
    }
}

// ---------------------------------------------------------------------------
// Kernel 2: per-edge logits -> segment softmax -> weighted aggregate.
// 4 nodes per 256-thread block; 64 threads per node; float4 coalesced gather.
// col_id dtype (int32 vs int64) sniffed at runtime: int64 high words are 0.
// ---------------------------------------------------------------------------
__global__ void __launch_bounds__(256) gat_kernel(const int* __restrict__ col32,
                                                  float* __restrict__ out)
{
    __shared__ int   s_src[4][DEG];
    __shared__ float s_alpha[4][HEADS][DEG];
    __shared__ int   s_is64;

    const int tid = threadIdx.x;
    if (tid == 0) {
        s_is64 = ((col32[1] | col32[3] | col32[5]) == 0) ? 1 : 0;
    }
    __syncthreads();

    const int g    = tid >> 6;
    const int t    = tid & 63;
    const int node = blockIdx.x * 4 + g;
    const int is64 = s_is64;

    if (t < DEG) {
        int e = node * DEG + t;
        s_src[g][t] = is64 ? col32[2 * e] : col32[e];
    }
    __syncthreads();

    {
        int e  = t >> 2;
        int hh = t & 3;
        int src = s_src[g][e];
        float v = g_ai[node * HEADS + hh] + g_aj[src * HEADS + hh];
        v = (v > 0.f) ? v : v * NEG_SLOPE;
        s_alpha[g][hh][e] = v;
    }
    __syncthreads();

    if (t < HEADS) {
        int hh = t;
        float m = -3.402823466e+38f;
#pragma unroll
        for (int e = 0; e < DEG; e++) m = fmaxf(m, s_alpha[g][hh][e]);
        float p[DEG];
        float s = 0.f;
#pragma unroll
        for (int e = 0; e < DEG; e++) { p[e] = expf(s_alpha[g][hh][e] - m); s += p[e]; }
        float inv = 1.f / (s + 1e-16f);
#pragma unroll
        for (int e = 0; e < DEG; e++) s_alpha[g][hh][e] = p[e] * inv;
    }
    __syncthreads();

    const int hh = t >> 4;
    float4 acc = make_float4(0.f, 0.f, 0.f, 0.f);
#pragma unroll
    for (int e = 0; e < DEG; e++) {
        float a = s_alpha[g][hh][e];
        const float4* hv = (const float4*)(g_h + (size_t)s_src[g][e] * HF);
        float4 v = hv[t];
        acc.x += a * v.x;  acc.y += a * v.y;
        acc.z += a * v.z;  acc.w += a * v.w;
    }
    ((float4*)out)[node * (HF / 4) + t] = acc;
}

// ---------------------------------------------------------------------------
// Launch: inputs in metadata order:
//   0: x [N,256] f32   1: row_id (unused)   2: row_ptr (unused)
//   3: col_id [E]      4: W [256,256] f32   5: att_i [1,4,64]   6: att_j [1,4,64]
// ---------------------------------------------------------------------------
extern "C" void kernel_launch(void* const* d_in, const int* in_sizes, int n_in,
                              void* d_out, int out_size)
{
    const float* x     = (const float*)d_in[0];
    const int*   col   = (const int*)  d_in[3];
    const float* W     = (const float*)d_in[4];
    const float* att_i = (const float*)d_in[5];
    const float* att_j = (const float*)d_in[6];
    float*       out   = (float*)d_out;

    cudaFuncSetAttribute(gemm_mma_kernel,
                         cudaFuncAttributeMaxDynamicSharedMemorySize,
                         GEMM_SMEM);

    dim3 grid(2, (N_NODES + 127) / 128);   // (2, 391)
    gemm_mma_kernel<<<grid, GT, GEMM_SMEM>>>(x, W, att_i, att_j);

    gat_kernel<<<N_NODES / 4, 256>>>(col, out);
}

// round 4
// speedup vs baseline: 1.9887x; 1.1115x over previous
#include <cuda_runtime.h>
#include <cuda_bf16.h>
#include <cstdint>

// Problem constants (fixed by the reference setup)
#define N_NODES 50000
#define NPAD    50048        // padded to 128-row multiple
#define DEG     16
#define IN_F    256
#define HEADS   4
#define OUT_F   64
#define HF      256          // HEADS * OUT_F
#define NEG_SLOPE 0.2f

// Scratch (allocation-free rule: __device__ globals)
__device__ float g_h [N_NODES * HF];            // projected features, 51.2 MB
__device__ float g_ai[N_NODES * HEADS];
__device__ float g_aj[N_NODES * HEADS];
__device__ __nv_bfloat16 g_xhi[NPAD * IN_F];    // 25.6 MB
__device__ __nv_bfloat16 g_xlo[NPAD * IN_F];
__device__ __nv_bfloat16 g_whi[HF * IN_F];      // 128 KB
__device__ __nv_bfloat16 g_wlo[HF * IN_F];

// ===========================================================================
// helpers
// ===========================================================================
__device__ __forceinline__ uint32_t smem_to_u32(const void* p) {
    uint32_t a;
    asm("{ .reg .u64 t; cvta.to.shared.u64 t, %1; cvt.u32.u64 %0, t; }"
        : "=r"(a) : "l"(p));
    return a;
}
__device__ __forceinline__ void ldsm4(uint32_t* r, uint32_t addr) {
    asm volatile("ldmatrix.sync.aligned.m8n8.x4.shared.b16 {%0,%1,%2,%3}, [%4];"
                 : "=r"(r[0]), "=r"(r[1]), "=r"(r[2]), "=r"(r[3]) : "r"(addr));
}
__device__ __forceinline__ void mma_bf16(float* d, const uint32_t* a,
                                         uint32_t b0, uint32_t b1) {
    asm volatile("mma.sync.aligned.m16n8k16.row.col.f32.bf16.bf16.f32 "
                 "{%0,%1,%2,%3}, {%4,%5,%6,%7}, {%8,%9}, {%0,%1,%2,%3};"
                 : "+f"(d[0]), "+f"(d[1]), "+f"(d[2]), "+f"(d[3])
                 : "r"(a[0]), "r"(a[1]), "r"(a[2]), "r"(a[3]), "r"(b0), "r"(b1));
}
__device__ __forceinline__ void cp16(uint32_t dst, const void* src) {
    asm volatile("cp.async.cg.shared.global [%0], [%1], 16;"
                 :: "r"(dst), "l"(src));
}
#define CP_COMMIT() asm volatile("cp.async.commit_group;")
#define CP_WAIT(n)  asm volatile("cp.async.wait_group %0;" :: "n"(n))

__device__ __forceinline__ uint32_t pack_bf2(__nv_bfloat16 a, __nv_bfloat16 b) {
    __nv_bfloat162 t; t.x = a; t.y = b;
    return *reinterpret_cast<uint32_t*>(&t);
}
__device__ __forceinline__ void split4(float4 v, uint2& hi, uint2& lo) {
    __nv_bfloat16 hx = __float2bfloat16(v.x), hy = __float2bfloat16(v.y);
    __nv_bfloat16 hz = __float2bfloat16(v.z), hw = __float2bfloat16(v.w);
    hi.x = pack_bf2(hx, hy);
    hi.y = pack_bf2(hz, hw);
    lo.x = pack_bf2(__float2bfloat16(v.x - __bfloat162float(hx)),
                    __float2bfloat16(v.y - __bfloat162float(hy)));
    lo.y = pack_bf2(__float2bfloat16(v.z - __bfloat162float(hz)),
                    __float2bfloat16(v.w - __bfloat162float(hw)));
}

// ===========================================================================
// Kernel 0: one-shot hi/lo bf16 split of x (padded+zero-filled) and W
// ===========================================================================
#define XQ (NPAD * IN_F / 4)     // float4 count for x
#define WQ (HF * IN_F / 4)
__global__ void __launch_bounds__(256)
convert_kernel(const float* __restrict__ x, const float* __restrict__ W)
{
    int idx = blockIdx.x * 256 + threadIdx.x;
    if (idx < XQ) {
        int row = idx >> 6;              // 64 float4 per row
        float4 v = (row < N_NODES)
                 ? reinterpret_cast<const float4*>(x)[idx]
                 : make_float4(0.f, 0.f, 0.f, 0.f);
        uint2 hi, lo;
        split4(v, hi, lo);
        reinterpret_cast<uint2*>(g_xhi)[idx] = hi;
        reinterpret_cast<uint2*>(g_xlo)[idx] = lo;
    } else if (idx - XQ < WQ) {
        int w = idx - XQ;
        uint2 hi, lo;
        split4(reinterpret_cast<const float4*>(W)[w], hi, lo);
        reinterpret_cast<uint2*>(g_whi)[w] = hi;
        reinterpret_cast<uint2*>(g_wlo)[w] = lo;
    }
}

// ===========================================================================
// Kernel 1: cp.async double-buffered bf16 split GEMM
// g_h = x @ W^T  (M=50048, N=256, K=256);  hi*hi + lo*hi + hi*lo.
// CTA tile 128x128 (grid 2 x 391), 8 warps (4M x 2N), warp tile 32x64,
// K staged by 64, 2-deep SMEM pipeline. Fused g_ai/g_aj epilogue.
// ===========================================================================
#define GT        256
#define STRB      144                     // smem row stride in bytes (64+8 bf16)
#define TILE_B    (128 * STRB)            // 18432 B
#define OFF_AHI   0
#define OFF_ALO   (TILE_B)
#define OFF_BHI   (2 * TILE_B)
#define OFF_BLO   (3 * TILE_B)
#define BUF_B     (4 * TILE_B)            // 73728 B per stage buffer
#define GEMM_SMEM (2 * BUF_B)             // 147456 B

extern __shared__ char g_smem[];

__global__ void __launch_bounds__(GT)
gemm_mma_kernel(const float* __restrict__ att_i, const float* __restrict__ att_j)
{
    const int tid  = threadIdx.x;
    const int wid  = tid >> 5;
    const int lane = tid & 31;
    const int wm   = wid >> 1;
    const int wn   = wid & 1;
    const int bx   = blockIdx.x;          // N block (0,1)
    const int m0   = blockIdx.y * 128;

    const uint32_t sb = smem_to_u32(g_smem);

    // per-thread cp.async chunk coords (4 chunks of 16B per tile)
    // chunk c in [0,1024): row=c>>3, col16=c&7
    const char* xhi = reinterpret_cast<const char*>(g_xhi);
    const char* xlo = reinterpret_cast<const char*>(g_xlo);
    const char* whi = reinterpret_cast<const char*>(g_whi);
    const char* wlo = reinterpret_cast<const char*>(g_wlo);

#define STAGE_LOAD(s, buf)                                                     \
    do {                                                                       \
        const int _k0b = (s) * 128;  /* 64 bf16 = 128 bytes */                 \
        const uint32_t _d0 = sb + (buf) * BUF_B;                               \
        _Pragma("unroll")                                                      \
        for (int _c = tid; _c < 1024; _c += GT) {                              \
            int _row = _c >> 3, _col = (_c & 7) * 16;                          \
            uint32_t _d = _d0 + (uint32_t)_row * STRB + _col;                  \
            size_t _ao = (size_t)(m0 + _row) * 512 + _k0b + _col;              \
            size_t _bo = (size_t)(bx * 128 + _row) * 512 + _k0b + _col;        \
            cp16(_d + OFF_AHI, xhi + _ao);                                     \
            cp16(_d + OFF_ALO, xlo + _ao);                                     \
            cp16(_d + OFF_BHI, whi + _bo);                                     \
            cp16(_d + OFF_BLO, wlo + _bo);                                     \
        }                                                                      \
        CP_COMMIT();                                                           \
    } while (0)

    float acc[2][8][4] = {};

    STAGE_LOAD(0, 0);

    for (int s = 0; s < 4; s++) {
        const int buf = s & 1;
        if (s < 3) {
            STAGE_LOAD(s + 1, buf ^ 1);
            CP_WAIT(1);
        } else {
            CP_WAIT(0);
        }
        __syncthreads();

        const uint32_t bbuf = sb + buf * BUF_B;
        const uint32_t aHI = bbuf + OFF_AHI, aLO = bbuf + OFF_ALO;
        const uint32_t bHI = bbuf + OFF_BHI, bLO = bbuf + OFF_BLO;

#pragma unroll
        for (int ks = 0; ks < 4; ks++) {
            const uint32_t kb = (uint32_t)ks * 32;

            uint32_t aoff = (uint32_t)(wm * 32 + (lane & 15)) * STRB
                          + kb + ((lane >> 4) << 4);
            uint32_t Ah0[4], Ah1[4], Al0[4], Al1[4];
            ldsm4(Ah0, aHI + aoff);
            ldsm4(Ah1, aHI + aoff + 16 * STRB);
            ldsm4(Al0, aLO + aoff);
            ldsm4(Al1, aLO + aoff + 16 * STRB);

            uint32_t nrow = (uint32_t)(wn * 64) + (lane & 7) + ((lane >> 4) << 3);
            uint32_t khalf = (lane >> 3) & 1;
            uint32_t bbase = nrow * STRB + kb + khalf * 16;
#pragma unroll
            for (int p = 0; p < 4; p++) {
                uint32_t boff = bbase + (uint32_t)p * 16 * STRB;
                uint32_t Bh[4], Bl[4];
                ldsm4(Bh, bHI + boff);
                ldsm4(Bl, bLO + boff);
#pragma unroll
                for (int h = 0; h < 2; h++) {
                    const int nt = p * 2 + h;
                    uint32_t bh0 = Bh[h * 2], bh1 = Bh[h * 2 + 1];
                    uint32_t bl0 = Bl[h * 2], bl1 = Bl[h * 2 + 1];
                    mma_bf16(acc[0][nt], Ah0, bh0, bh1);
                    mma_bf16(acc[1][nt], Ah1, bh0, bh1);
                    mma_bf16(acc[0][nt], Al0, bh0, bh1);
                    mma_bf16(acc[1][nt], Al1, bh0, bh1);
                    mma_bf16(acc[0][nt], Ah0, bl0, bl1);
                    mma_bf16(acc[1][nt], Ah1, bl0, bl1);
                }
            }
        }
        __syncthreads();
    }

    // ---- epilogue: write g_h + fused attention dots ----
    const int head    = bx * 2 + wn;
    const int colbase = bx * 128 + wn * 64;
    const int rbase   = m0 + wm * 32 + (lane >> 2);
    float si[2][2] = {}, sj[2][2] = {};

#pragma unroll
    for (int nt = 0; nt < 8; nt++) {
        const int g = colbase + nt * 8 + (lane & 3) * 2;
        const float ai0 = att_i[g], ai1 = att_i[g + 1];
        const float aj0 = att_j[g], aj1 = att_j[g + 1];
#pragma unroll
        for (int mt = 0; mt < 2; mt++) {
            si[mt][0] += acc[mt][nt][0] * ai0 + acc[mt][nt][1] * ai1;
            sj[mt][0] += acc[mt][nt][0] * aj0 + acc[mt][nt][1] * aj1;
            si[mt][1] += acc[mt][nt][2] * ai0 + acc[mt][nt][3] * ai1;
            sj[mt][1] += acc[mt][nt][2] * aj0 + acc[mt][nt][3] * aj1;
            const int r0 = rbase + mt * 16;
            if (r0 < N_NODES)
                *reinterpret_cast<float2*>(g_h + (size_t)r0 * HF + g)
                    = make_float2(acc[mt][nt][0], acc[mt][nt][1]);
            const int r1 = r0 + 8;
            if (r1 < N_NODES)
                *reinterpret_cast<float2*>(g_h + (size_t)r1 * HF + g)
                    = make_float2(acc[mt][nt][2], acc[mt][nt][3]);
        }
    }
#pragma unroll
    for (int off = 1; off <= 2; off <<= 1) {
#pragma unroll
        for (int mt = 0; mt < 2; mt++)
#pragma unroll
            for (int hf = 0; hf < 2; hf++) {
                si[mt][hf] += __shfl_xor_sync(0xffffffffu, si[mt][hf], off);
                sj[mt][hf] += __shfl_xor_sync(0xffffffffu, sj[mt][hf], off);
            }
    }
    if ((lane & 3) == 0) {
#pragma unroll
        for (int mt = 0; mt < 2; mt++)
#pragma unroll
            for (int hf = 0; hf < 2; hf++) {
                const int r = rbase + mt * 16 + hf * 8;
                if (r < N_NODES) {
                    g_ai[(size_t)r * HEADS + head] = si[mt][hf];
                    g_aj[(size_t)r * HEADS + head] = sj[mt][hf];
                }
            }
    }
}

// ---------------------------------------------------------------------------
// Kernel 2: per-edge logits -> segment softmax -> weighted aggregate.
// ---------------------------------------------------------------------------
__global__ void __launch_bounds__(256) gat_kernel(const int* __restrict__ col32,
                                                  float* __restrict__ out)
{
    __shared__ int   s_src[4][DEG];
    __shared__ float s_alpha[4][HEADS][DEG];
    __shared__ int   s_is64;

    const int tid = threadIdx.x;
    if (tid == 0) {
        s_is64 = ((col32[1] | col32[3] | col32[5]) == 0) ? 1 : 0;
    }
    __syncthreads();

    const int g    = tid >> 6;
    const int t    = tid & 63;
    const int node = blockIdx.x * 4 + g;
    const int is64 = s_is64;

    if (t < DEG) {
        int e = node * DEG + t;
        s_src[g][t] = is64 ? col32[2 * e] : col32[e];
    }
    __syncthreads();

    {
        int e  = t >> 2;
        int hh = t & 3;
        int src = s_src[g][e];
        float v = g_ai[node * HEADS + hh] + g_aj[src * HEADS + hh];
        v = (v > 0.f) ? v : v * NEG_SLOPE;
        s_alpha[g][hh][e] = v;
    }
    __syncthreads();

    if (t < HEADS) {
        int hh = t;
        float m = -3.402823466e+38f;
#pragma unroll
        for (int e = 0; e < DEG; e++) m = fmaxf(m, s_alpha[g][hh][e]);
        float p[DEG];
        float s = 0.f;
#pragma unroll
        for (int e = 0; e < DEG; e++) { p[e] = expf(s_alpha[g][hh][e] - m); s += p[e]; }
        float inv = 1.f / (s + 1e-16f);
#pragma unroll
        for (int e = 0; e < DEG; e++) s_alpha[g][hh][e] = p[e] * inv;
    }
    __syncthreads();

    const int hh = t >> 4;
    float4 acc = make_float4(0.f, 0.f, 0.f, 0.f);
#pragma unroll
    for (int e = 0; e < DEG; e++) {
        float a = s_alpha[g][hh][e];
        const float4* hv = (const float4*)(g_h + (size_t)s_src[g][e] * HF);
        float4 v = hv[t];
        acc.x += a * v.x;  acc.y += a * v.y;
        acc.z += a * v.z;  acc.w += a * v.w;
    }
    ((float4*)out)[node * (HF / 4) + t] = acc;
}

// ---------------------------------------------------------------------------
// Launch: inputs in metadata order:
//   0: x   1: row_id (unused)   2: row_ptr (unused)
//   3: col_id   4: W   5: att_i   6: att_j
// ---------------------------------------------------------------------------
extern "C" void kernel_launch(void* const* d_in, const int* in_sizes, int n_in,
                              void* d_out, int out_size)
{
    const float* x     = (const float*)d_in[0];
    const int*   col   = (const int*)  d_in[3];
    const float* W     = (const float*)d_in[4];
    const float* att_i = (const float*)d_in[5];
    const float* att_j = (const float*)d_in[6];
    float*       out   = (float*)d_out;

    cudaFuncSetAttribute(gemm_mma_kernel,
                         cudaFuncAttributeMaxDynamicSharedMemorySize,
                         GEMM_SMEM);

    convert_kernel<<<(XQ + WQ + 255) / 256, 256>>>(x, W);

    dim3 grid(2, NPAD / 128);              // (2, 391)
    gemm_mma_kernel<<<grid, GT, GEMM_SMEM>>>(att_i, att_j);

    gat_kernel<<<N_NODES / 4, 256>>>(col, out);
}

// round 5
// speedup vs baseline: 2.1950x; 1.1037x over previous
#include <cuda_runtime.h>
#include <cuda_fp16.h>
#include <cuda_bf16.h>
#include <cstdint>

// Problem constants (fixed by the reference setup)
#define N_NODES 50000
#define NPAD    50176        // padded to 256-row multiple
#define DEG     16
#define IN_F    256
#define HEADS   4
#define OUT_F   64
#define HF      256          // HEADS * OUT_F
#define NEG_SLOPE 0.2f

// Scratch (allocation-free rule: __device__ globals)
__device__ __half g_hh[N_NODES * HF];           // projected features, fp16, 25.6 MB
__device__ float g_ai[N_NODES * HEADS];
__device__ float g_aj[N_NODES * HEADS];
__device__ __nv_bfloat16 g_xhi[NPAD * IN_F];    // 25.7 MB
__device__ __nv_bfloat16 g_xlo[NPAD * IN_F];
__device__ __nv_bfloat16 g_whi[HF * IN_F];      // 128 KB
__device__ __nv_bfloat16 g_wlo[HF * IN_F];

// ===========================================================================
// helpers
// ===========================================================================
__device__ __forceinline__ uint32_t smem_to_u32(const void* p) {
    uint32_t a;
    asm("{ .reg .u64 t; cvta.to.shared.u64 t, %1; cvt.u32.u64 %0, t; }"
        : "=r"(a) : "l"(p));
    return a;
}
__device__ __forceinline__ void ldsm4(uint32_t* r, uint32_t addr) {
    asm volatile("ldmatrix.sync.aligned.m8n8.x4.shared.b16 {%0,%1,%2,%3}, [%4];"
                 : "=r"(r[0]), "=r"(r[1]), "=r"(r[2]), "=r"(r[3]) : "r"(addr));
}
__device__ __forceinline__ void mma_bf16(float* d, const uint32_t* a,
                                         uint32_t b0, uint32_t b1) {
    asm volatile("mma.sync.aligned.m16n8k16.row.col.f32.bf16.bf16.f32 "
                 "{%0,%1,%2,%3}, {%4,%5,%6,%7}, {%8,%9}, {%0,%1,%2,%3};"
                 : "+f"(d[0]), "+f"(d[1]), "+f"(d[2]), "+f"(d[3])
                 : "r"(a[0]), "r"(a[1]), "r"(a[2]), "r"(a[3]), "r"(b0), "r"(b1));
}
__device__ __forceinline__ void cp16(uint32_t dst, const void* src) {
    asm volatile("cp.async.cg.shared.global [%0], [%1], 16;"
                 :: "r"(dst), "l"(src));
}
#define CP_COMMIT() asm volatile("cp.async.commit_group;")
#define CP_WAIT(n)  asm volatile("cp.async.wait_group %0;" :: "n"(n))

__device__ __forceinline__ uint32_t pack_bf2(__nv_bfloat16 a, __nv_bfloat16 b) {
    __nv_bfloat162 t; t.x = a; t.y = b;
    return *reinterpret_cast<uint32_t*>(&t);
}
__device__ __forceinline__ void split4(float4 v, uint2& hi, uint2& lo) {
    __nv_bfloat16 hx = __float2bfloat16(v.x), hy = __float2bfloat16(v.y);
    __nv_bfloat16 hz = __float2bfloat16(v.z), hw = __float2bfloat16(v.w);
    hi.x = pack_bf2(hx, hy);
    hi.y = pack_bf2(hz, hw);
    lo.x = pack_bf2(__float2bfloat16(v.x - __bfloat162float(hx)),
                    __float2bfloat16(v.y - __bfloat162float(hy)));
    lo.y = pack_bf2(__float2bfloat16(v.z - __bfloat162float(hz)),
                    __float2bfloat16(v.w - __bfloat162float(hw)));
}

// ===========================================================================
// Kernel 0: one-shot hi/lo bf16 split of x (padded+zero-filled) and W
// ===========================================================================
#define XQ (NPAD * IN_F / 4)
#define WQ (HF * IN_F / 4)
__global__ void __launch_bounds__(256)
convert_kernel(const float* __restrict__ x, const float* __restrict__ W)
{
    int idx = blockIdx.x * 256 + threadIdx.x;
    if (idx < XQ) {
        int row = idx >> 6;
        float4 v = (row < N_NODES)
                 ? reinterpret_cast<const float4*>(x)[idx]
                 : make_float4(0.f, 0.f, 0.f, 0.f);
        uint2 hi, lo;
        split4(v, hi, lo);
        reinterpret_cast<uint2*>(g_xhi)[idx] = hi;
        reinterpret_cast<uint2*>(g_xlo)[idx] = lo;
    } else if (idx - XQ < WQ) {
        int w = idx - XQ;
        uint2 hi, lo;
        split4(reinterpret_cast<const float4*>(W)[w], hi, lo);
        reinterpret_cast<uint2*>(g_whi)[w] = hi;
        reinterpret_cast<uint2*>(g_wlo)[w] = lo;
    }
}

// ===========================================================================
// Kernel 1: cp.async double-buffered bf16 split GEMM
// g_hh = x @ W^T (M=50176, N=256, K=256); hi*hi + lo*hi + hi*lo, fp32 acc.
// CTA tile 256x128 (grid 2 x 196), 16 warps (8M x 2N), warp tile 32x64,
// K staged by 64, 2-deep SMEM pipeline. Fused g_ai/g_aj epilogue (fp32).
// ===========================================================================
#define GT        512
#define STRB      144                     // smem row stride in bytes (64+8 bf16)
#define TILE_A    (256 * STRB)            // 36864 B
#define TILE_W    (128 * STRB)            // 18432 B
#define OFF_AHI   0
#define OFF_ALO   (TILE_A)
#define OFF_BHI   (2 * TILE_A)
#define OFF_BLO   (2 * TILE_A + TILE_W)
#define BUF_B     (2 * TILE_A + 2 * TILE_W)   // 110592 B per stage
#define GEMM_SMEM (2 * BUF_B)                 // 221184 B

extern __shared__ char g_smem[];

__global__ void __launch_bounds__(GT)
gemm_mma_kernel(const float* __restrict__ att_i, const float* __restrict__ att_j)
{
    const int tid  = threadIdx.x;
    const int wid  = tid >> 5;
    const int lane = tid & 31;
    const int wm   = wid >> 1;            // 0..7 (M dim)
    const int wn   = wid & 1;             // 0..1 (N dim)
    const int bx   = blockIdx.x;          // N block (0,1)
    const int m0   = blockIdx.y * 256;

    const uint32_t sb = smem_to_u32(g_smem);

    const char* xhi = reinterpret_cast<const char*>(g_xhi);
    const char* xlo = reinterpret_cast<const char*>(g_xlo);
    const char* whi = reinterpret_cast<const char*>(g_whi);
    const char* wlo = reinterpret_cast<const char*>(g_wlo);

#define STAGE_LOAD(s, buf)                                                     \
    do {                                                                       \
        const int _k0b = (s) * 128;  /* 64 bf16 = 128 bytes */                 \
        const uint32_t _d0 = sb + (buf) * BUF_B;                               \
        _Pragma("unroll")                                                      \
        for (int _c = tid; _c < 2048; _c += GT) {     /* A: 256 rows */        \
            int _row = _c >> 3, _col = (_c & 7) * 16;                          \
            uint32_t _d = _d0 + (uint32_t)_row * STRB + _col;                  \
            size_t _ao = (size_t)(m0 + _row) * 512 + _k0b + _col;              \
            cp16(_d + OFF_AHI, xhi + _ao);                                     \
            cp16(_d + OFF_ALO, xlo + _ao);                                     \
        }                                                                      \
        _Pragma("unroll")                                                      \
        for (int _c = tid; _c < 1024; _c += GT) {     /* B: 128 rows */        \
            int _row = _c >> 3, _col = (_c & 7) * 16;                          \
            uint32_t _d = _d0 + (uint32_t)_row * STRB + _col;                  \
            size_t _bo = (size_t)(bx * 128 + _row) * 512 + _k0b + _col;        \
            cp16(_d + OFF_BHI, whi + _bo);                                     \
            cp16(_d + OFF_BLO, wlo + _bo);                                     \
        }                                                                      \
        CP_COMMIT();                                                           \
    } while (0)

    float acc[2][8][4] = {};

    STAGE_LOAD(0, 0);

    for (int s = 0; s < 4; s++) {
        const int buf = s & 1;
        if (s < 3) {
            STAGE_LOAD(s + 1, buf ^ 1);
            CP_WAIT(1);
        } else {
            CP_WAIT(0);
        }
        __syncthreads();

        const uint32_t bbuf = sb + buf * BUF_B;
        const uint32_t aHI = bbuf + OFF_AHI, aLO = bbuf + OFF_ALO;
        const uint32_t bHI = bbuf + OFF_BHI, bLO = bbuf + OFF_BLO;

#pragma unroll
        for (int ks = 0; ks < 4; ks++) {
            const uint32_t kb = (uint32_t)ks * 32;

            uint32_t aoff = (uint32_t)(wm * 32 + (lane & 15)) * STRB
                          + kb + ((lane >> 4) << 4);
            uint32_t Ah0[4], Ah1[4], Al0[4], Al1[4];
            ldsm4(Ah0, aHI + aoff);
            ldsm4(Ah1, aHI + aoff + 16 * STRB);
            ldsm4(Al0, aLO + aoff);
            ldsm4(Al1, aLO + aoff + 16 * STRB);

            uint32_t nrow = (uint32_t)(wn * 64) + (lane & 7) + ((lane >> 4) << 3);
            uint32_t khalf = (lane >> 3) & 1;
            uint32_t bbase = nrow * STRB + kb + khalf * 16;
#pragma unroll
            for (int p = 0; p < 4; p++) {
                uint32_t boff = bbase + (uint32_t)p * 16 * STRB;
                uint32_t Bh[4], Bl[4];
                ldsm4(Bh, bHI + boff);
                ldsm4(Bl, bLO + boff);
#pragma unroll
                for (int h = 0; h < 2; h++) {
                    const int nt = p * 2 + h;
                    uint32_t bh0 = Bh[h * 2], bh1 = Bh[h * 2 + 1];
                    uint32_t bl0 = Bl[h * 2], bl1 = Bl[h * 2 + 1];
                    mma_bf16(acc[0][nt], Ah0, bh0, bh1);
                    mma_bf16(acc[1][nt], Ah1, bh0, bh1);
                    mma_bf16(acc[0][nt], Al0, bh0, bh1);
                    mma_bf16(acc[1][nt], Al1, bh0, bh1);
                    mma_bf16(acc[0][nt], Ah0, bl0, bl1);
                    mma_bf16(acc[1][nt], Ah1, bl0, bl1);
                }
            }
        }
        __syncthreads();
    }

    // ---- epilogue: write g_hh (fp16) + fused attention dots (fp32) ----
    const int head    = bx * 2 + wn;
    const int colbase = bx * 128 + wn * 64;
    const int rbase   = m0 + wm * 32 + (lane >> 2);
    float si[2][2] = {}, sj[2][2] = {};

#pragma unroll
    for (int nt = 0; nt < 8; nt++) {
        const int g = colbase + nt * 8 + (lane & 3) * 2;
        const float ai0 = att_i[g], ai1 = att_i[g + 1];
        const float aj0 = att_j[g], aj1 = att_j[g + 1];
#pragma unroll
        for (int mt = 0; mt < 2; mt++) {
            si[mt][0] += acc[mt][nt][0] * ai0 + acc[mt][nt][1] * ai1;
            sj[mt][0] += acc[mt][nt][0] * aj0 + acc[mt][nt][1] * aj1;
            si[mt][1] += acc[mt][nt][2] * ai0 + acc[mt][nt][3] * ai1;
            sj[mt][1] += acc[mt][nt][2] * aj0 + acc[mt][nt][3] * aj1;
            const int r0 = rbase + mt * 16;
            if (r0 < N_NODES)
                *reinterpret_cast<__half2*>(g_hh + (size_t)r0 * HF + g)
                    = __floats2half2_rn(acc[mt][nt][0], acc[mt][nt][1]);
            const int r1 = r0 + 8;
            if (r1 < N_NODES)
                *reinterpret_cast<__half2*>(g_hh + (size_t)r1 * HF + g)
                    = __floats2half2_rn(acc[mt][nt][2], acc[mt][nt][3]);
        }
    }
#pragma unroll
    for (int off = 1; off <= 2; off <<= 1) {
#pragma unroll
        for (int mt = 0; mt < 2; mt++)
#pragma unroll
            for (int hf = 0; hf < 2; hf++) {
                si[mt][hf] += __shfl_xor_sync(0xffffffffu, si[mt][hf], off);
                sj[mt][hf] += __shfl_xor_sync(0xffffffffu, sj[mt][hf], off);
            }
    }
    if ((lane & 3) == 0) {
#pragma unroll
        for (int mt = 0; mt < 2; mt++)
#pragma unroll
            for (int hf = 0; hf < 2; hf++) {
                const int r = rbase + mt * 16 + hf * 8;
                if (r < N_NODES) {
                    g_ai[(size_t)r * HEADS + head] = si[mt][hf];
                    g_aj[(size_t)r * HEADS + head] = sj[mt][hf];
                }
            }
    }
}

// ---------------------------------------------------------------------------
// Kernel 2: per-edge logits -> segment softmax -> weighted aggregate (fp16 h).
// 4 nodes per 256-thread block; 64 threads per node; uint2 (4-half) loads.
// ---------------------------------------------------------------------------
__global__ void __launch_bounds__(256) gat_kernel(const int* __restrict__ col32,
                                                  float* __restrict__ out)
{
    __shared__ int   s_src[4][DEG];
    __shared__ float s_alpha[4][HEADS][DEG];
    __shared__ int   s_is64;

    const int tid = threadIdx.x;
    if (tid == 0) {
        s_is64 = ((col32[1] | col32[3] | col32[5]) == 0) ? 1 : 0;
    }
    __syncthreads();

    const int g    = tid >> 6;
    const int t    = tid & 63;
    const int node = blockIdx.x * 4 + g;
    const int is64 = s_is64;

    if (t < DEG) {
        int e = node * DEG + t;
        s_src[g][t] = is64 ? col32[2 * e] : col32[e];
    }
    __syncthreads();

    {
        int e  = t >> 2;
        int hh = t & 3;
        int src = s_src[g][e];
        float v = g_ai[node * HEADS + hh] + g_aj[src * HEADS + hh];
        v = (v > 0.f) ? v : v * NEG_SLOPE;
        s_alpha[g][hh][e] = v;
    }
    __syncthreads();

    if (t < HEADS) {
        int hh = t;
        float m = -3.402823466e+38f;
#pragma unroll
        for (int e = 0; e < DEG; e++) m = fmaxf(m, s_alpha[g][hh][e]);
        float p[DEG];
        float s = 0.f;
#pragma unroll
        for (int e = 0; e < DEG; e++) { p[e] = expf(s_alpha[g][hh][e] - m); s += p[e]; }
        float inv = 1.f / (s + 1e-16f);
#pragma unroll
        for (int e = 0; e < DEG; e++) s_alpha[g][hh][e] = p[e] * inv;
    }
    __syncthreads();

    const int hh = t >> 4;
    float4 acc = make_float4(0.f, 0.f, 0.f, 0.f);
#pragma unroll
    for (int e = 0; e < DEG; e++) {
        float a = s_alpha[g][hh][e];
        const uint2* hv = (const uint2*)(g_hh + (size_t)s_src[g][e] * HF);
        uint2 u = hv[t];                        // 4 halves
        float2 f0 = __half22float2(*reinterpret_cast<__half2*>(&u.x));
        float2 f1 = __half22float2(*reinterpret_cast<__half2*>(&u.y));
        acc.x += a * f0.x;  acc.y += a * f0.y;
        acc.z += a * f1.x;  acc.w += a * f1.y;
    }
    ((float4*)out)[node * (HF / 4) + t] = acc;
}

// ---------------------------------------------------------------------------
// Launch: inputs in metadata order:
//   0: x   1: row_id (unused)   2: row_ptr (unused)
//   3: col_id   4: W   5: att_i   6: att_j
// ---------------------------------------------------------------------------
extern "C" void kernel_launch(void* const* d_in, const int* in_sizes, int n_in,
                              void* d_out, int out_size)
{
    const float* x     = (const float*)d_in[0];
    const int*   col   = (const int*)  d_in[3];
    const float* W     = (const float*)d_in[4];
    const float* att_i = (const float*)d_in[5];
    const float* att_j = (const float*)d_in[6];
    float*       out   = (float*)d_out;

    cudaFuncSetAttribute(gemm_mma_kernel,
                         cudaFuncAttributeMaxDynamicSharedMemorySize,
                         GEMM_SMEM);

    convert_kernel<<<(XQ + WQ + 255) / 256, 256>>>(x, W);

    dim3 grid(2, NPAD / 256);              // (2, 196)
    gemm_mma_kernel<<<grid, GT, GEMM_SMEM>>>(att_i, att_j);

    gat_kernel<<<N_NODES / 4, 256>>>(col, out);
}

// round 6
// speedup vs baseline: 3.0959x; 1.4105x over previous
#include <cuda_runtime.h>
#include <cuda_fp16.h>
#include <cstdint>

// Problem constants (fixed by the reference setup)
#define N_NODES 50000
#define NPAD    50176        // padded to 256-row multiple
#define DEG     16
#define IN_F    256
#define HEADS   4
#define OUT_F   64
#define HF      256          // HEADS * OUT_F
#define NEG_SLOPE 0.2f

// Scratch (allocation-free rule: __device__ globals)
__device__ __half g_hh[N_NODES * HF];      // projected features, fp16, 25.6 MB
__device__ float g_ai[N_NODES * HEADS];
__device__ float g_aj[N_NODES * HEADS];
__device__ __half g_xh[NPAD * IN_F];       // x in fp16, 25.7 MB
__device__ __half g_wh[HF * IN_F];         // W in fp16, 128 KB

// ===========================================================================
// helpers
// ===========================================================================
__device__ __forceinline__ uint32_t smem_to_u32(const void* p) {
    uint32_t a;
    asm("{ .reg .u64 t; cvta.to.shared.u64 t, %1; cvt.u32.u64 %0, t; }"
        : "=r"(a) : "l"(p));
    return a;
}
__device__ __forceinline__ void ldsm4(uint32_t* r, uint32_t addr) {
    asm volatile("ldmatrix.sync.aligned.m8n8.x4.shared.b16 {%0,%1,%2,%3}, [%4];"
                 : "=r"(r[0]), "=r"(r[1]), "=r"(r[2]), "=r"(r[3]) : "r"(addr));
}
__device__ __forceinline__ void mma_f16(float* d, const uint32_t* a,
                                        uint32_t b0, uint32_t b1) {
    asm volatile("mma.sync.aligned.m16n8k16.row.col.f32.f16.f16.f32 "
                 "{%0,%1,%2,%3}, {%4,%5,%6,%7}, {%8,%9}, {%0,%1,%2,%3};"
                 : "+f"(d[0]), "+f"(d[1]), "+f"(d[2]), "+f"(d[3])
                 : "r"(a[0]), "r"(a[1]), "r"(a[2]), "r"(a[3]), "r"(b0), "r"(b1));
}
__device__ __forceinline__ void cp16(uint32_t dst, const void* src) {
    asm volatile("cp.async.cg.shared.global [%0], [%1], 16;"
                 :: "r"(dst), "l"(src));
}
#define CP_COMMIT() asm volatile("cp.async.commit_group;")
#define CP_WAIT(n)  asm volatile("cp.async.wait_group %0;" :: "n"(n))

// ===========================================================================
// Kernel 0: one-shot fp16 conversion of x (padded+zero-filled) and W
// ===========================================================================
#define XQ (NPAD * IN_F / 4)
#define WQ (HF * IN_F / 4)
__global__ void __launch_bounds__(256)
convert_kernel(const float* __restrict__ x, const float* __restrict__ W)
{
    int idx = blockIdx.x * 256 + threadIdx.x;
    if (idx < XQ) {
        int row = idx >> 6;
        float4 v = (row < N_NODES)
                 ? reinterpret_cast<const float4*>(x)[idx]
                 : make_float4(0.f, 0.f, 0.f, 0.f);
        uint2 o;
        __half2 p0 = __floats2half2_rn(v.x, v.y);
        __half2 p1 = __floats2half2_rn(v.z, v.w);
        o.x = *reinterpret_cast<uint32_t*>(&p0);
        o.y = *reinterpret_cast<uint32_t*>(&p1);
        reinterpret_cast<uint2*>(g_xh)[idx] = o;
    } else if (idx - XQ < WQ) {
        int w = idx - XQ;
        float4 v = reinterpret_cast<const float4*>(W)[w];
        uint2 o;
        __half2 p0 = __floats2half2_rn(v.x, v.y);
        __half2 p1 = __floats2half2_rn(v.z, v.w);
        o.x = *reinterpret_cast<uint32_t*>(&p0);
        o.y = *reinterpret_cast<uint32_t*>(&p1);
        reinterpret_cast<uint2*>(g_wh)[w] = o;
    }
}

// ===========================================================================
// Kernel 1: cp.async double-buffered fp16 GEMM (single term)
// g_hh = x @ W^T (M=50176, N=256, K=256), fp32 accum.
// CTA tile 256x128 (grid 2 x 196), 16 warps (8M x 2N), warp tile 32x64,
// K staged by 64, 2-deep SMEM pipeline. Fused g_ai/g_aj epilogue (fp32).
// ===========================================================================
#define GT        512
#define STRB      144                     // smem row stride in bytes (64+8 fp16)
#define TILE_A    (256 * STRB)            // 36864 B
#define TILE_W    (128 * STRB)            // 18432 B
#define OFF_A     0
#define OFF_B     (TILE_A)
#define BUF_B     (TILE_A + TILE_W)       // 55296 B per stage
#define GEMM_SMEM (2 * BUF_B)             // 110592 B

extern __shared__ char g_smem[];

__global__ void __launch_bounds__(GT)
gemm_mma_kernel(const float* __restrict__ att_i, const float* __restrict__ att_j)
{
    const int tid  = threadIdx.x;
    const int wid  = tid >> 5;
    const int lane = tid & 31;
    const int wm   = wid >> 1;            // 0..7 (M dim)
    const int wn   = wid & 1;             // 0..1 (N dim)
    const int bx   = blockIdx.x;          // N block (0,1)
    const int m0   = blockIdx.y * 256;

    const uint32_t sb = smem_to_u32(g_smem);

    const char* xh = reinterpret_cast<const char*>(g_xh);
    const char* wh = reinterpret_cast<const char*>(g_wh);

#define STAGE_LOAD(s, buf)                                                     \
    do {                                                                       \
        const int _k0b = (s) * 128;  /* 64 fp16 = 128 bytes */                 \
        const uint32_t _d0 = sb + (buf) * BUF_B;                               \
        _Pragma("unroll")                                                      \
        for (int _c = tid; _c < 2048; _c += GT) {     /* A: 256 rows x 8 */    \
            int _row = _c >> 3, _col = (_c & 7) * 16;                          \
            uint32_t _d = _d0 + (uint32_t)_row * STRB + _col;                  \
            size_t _ao = (size_t)(m0 + _row) * 512 + _k0b + _col;              \
            cp16(_d + OFF_A, xh + _ao);                                        \
        }                                                                      \
        _Pragma("unroll")                                                      \
        for (int _c = tid; _c < 1024; _c += GT) {     /* B: 128 rows x 8 */    \
            int _row = _c >> 3, _col = (_c & 7) * 16;                          \
            uint32_t _d = _d0 + (uint32_t)_row * STRB + _col;                  \
            size_t _bo = (size_t)(bx * 128 + _row) * 512 + _k0b + _col;        \
            cp16(_d + OFF_B, wh + _bo);                                        \
        }                                                                      \
        CP_COMMIT();                                                           \
    } while (0)

    float acc[2][8][4] = {};

    STAGE_LOAD(0, 0);

    for (int s = 0; s < 4; s++) {
        const int buf = s & 1;
        if (s < 3) {
            STAGE_LOAD(s + 1, buf ^ 1);
            CP_WAIT(1);
        } else {
            CP_WAIT(0);
        }
        __syncthreads();

        const uint32_t bbuf = sb + buf * BUF_B;
        const uint32_t aB = bbuf + OFF_A, bB = bbuf + OFF_B;

#pragma unroll
        for (int ks = 0; ks < 4; ks++) {
            const uint32_t kb = (uint32_t)ks * 32;

            uint32_t aoff = (uint32_t)(wm * 32 + (lane & 15)) * STRB
                          + kb + ((lane >> 4) << 4);
            uint32_t A0[4], A1[4];
            ldsm4(A0, aB + aoff);
            ldsm4(A1, aB + aoff + 16 * STRB);

            uint32_t nrow = (uint32_t)(wn * 64) + (lane & 7) + ((lane >> 4) << 3);
            uint32_t khalf = (lane >> 3) & 1;
            uint32_t bbase = nrow * STRB + kb + khalf * 16;
#pragma unroll
            for (int p = 0; p < 4; p++) {
                uint32_t Bf[4];
                ldsm4(Bf, bB + bbase + (uint32_t)p * 16 * STRB);
#pragma unroll
                for (int h = 0; h < 2; h++) {
                    const int nt = p * 2 + h;
                    mma_f16(acc[0][nt], A0, Bf[h * 2], Bf[h * 2 + 1]);
                    mma_f16(acc[1][nt], A1, Bf[h * 2], Bf[h * 2 + 1]);
                }
            }
        }
        __syncthreads();
    }

    // ---- epilogue: write g_hh (fp16) + fused attention dots (fp32) ----
    const int head    = bx * 2 + wn;
    const int colbase = bx * 128 + wn * 64;
    const int rbase   = m0 + wm * 32 + (lane >> 2);
    float si[2][2] = {}, sj[2][2] = {};

#pragma unroll
    for (int nt = 0; nt < 8; nt++) {
        const int g = colbase + nt * 8 + (lane & 3) * 2;
        const float ai0 = att_i[g], ai1 = att_i[g + 1];
        const float aj0 = att_j[g], aj1 = att_j[g + 1];
#pragma unroll
        for (int mt = 0; mt < 2; mt++) {
            si[mt][0] += acc[mt][nt][0] * ai0 + acc[mt][nt][1] * ai1;
            sj[mt][0] += acc[mt][nt][0] * aj0 + acc[mt][nt][1] * aj1;
            si[mt][1] += acc[mt][nt][2] * ai0 + acc[mt][nt][3] * ai1;
            sj[mt][1] += acc[mt][nt][2] * aj0 + acc[mt][nt][3] * aj1;
            const int r0 = rbase + mt * 16;
            if (r0 < N_NODES)
                *reinterpret_cast<__half2*>(g_hh + (size_t)r0 * HF + g)
                    = __floats2half2_rn(acc[mt][nt][0], acc[mt][nt][1]);
            const int r1 = r0 + 8;
            if (r1 < N_NODES)
                *reinterpret_cast<__half2*>(g_hh + (size_t)r1 * HF + g)
                    = __floats2half2_rn(acc[mt][nt][2], acc[mt][nt][3]);
        }
    }
#pragma unroll
    for (int off = 1; off <= 2; off <<= 1) {
#pragma unroll
        for (int mt = 0; mt < 2; mt++)
#pragma unroll
            for (int hf = 0; hf < 2; hf++) {
                si[mt][hf] += __shfl_xor_sync(0xffffffffu, si[mt][hf], off);
                sj[mt][hf] += __shfl_xor_sync(0xffffffffu, sj[mt][hf], off);
            }
    }
    if ((lane & 3) == 0) {
#pragma unroll
        for (int mt = 0; mt < 2; mt++)
#pragma unroll
            for (int hf = 0; hf < 2; hf++) {
                const int r = rbase + mt * 16 + hf * 8;
                if (r < N_NODES) {
                    g_ai[(size_t)r * HEADS + head] = si[mt][hf];
                    g_aj[(size_t)r * HEADS + head] = sj[mt][hf];
                }
            }
    }
}

// ---------------------------------------------------------------------------
// Kernel 2: per-edge logits -> segment softmax -> weighted aggregate (fp16 h).
// 4 nodes per 256-thread block; 64 threads per node; uint2 (4-half) loads.
// ---------------------------------------------------------------------------
__global__ void __launch_bounds__(256) gat_kernel(const int* __restrict__ col32,
                                                  float* __restrict__ out)
{
    __shared__ int   s_src[4][DEG];
    __shared__ float s_alpha[4][HEADS][DEG];
    __shared__ int   s_is64;

    const int tid = threadIdx.x;
    if (tid == 0) {
        s_is64 = ((col32[1] | col32[3] | col32[5]) == 0) ? 1 : 0;
    }
    __syncthreads();

    const int g    = tid >> 6;
    const int t    = tid & 63;
    const int node = blockIdx.x * 4 + g;
    const int is64 = s_is64;

    if (t < DEG) {
        int e = node * DEG + t;
        s_src[g][t] = is64 ? col32[2 * e] : col32[e];
    }
    __syncthreads();

    {
        int e  = t >> 2;
        int hh = t & 3;
        int src = s_src[g][e];
        float v = g_ai[node * HEADS + hh] + g_aj[src * HEADS + hh];
        v = (v > 0.f) ? v : v * NEG_SLOPE;
        s_alpha[g][hh][e] = v;
    }
    __syncthreads();

    if (t < HEADS) {
        int hh = t;
        float m = -3.402823466e+38f;
#pragma unroll
        for (int e = 0; e < DEG; e++) m = fmaxf(m, s_alpha[g][hh][e]);
        float p[DEG];
        float s = 0.f;
#pragma unroll
        for (int e = 0; e < DEG; e++) { p[e] = expf(s_alpha[g][hh][e] - m); s += p[e]; }
        float inv = 1.f / (s + 1e-16f);
#pragma unroll
        for (int e = 0; e < DEG; e++) s_alpha[g][hh][e] = p[e] * inv;
    }
    __syncthreads();

    const int hh = t >> 4;
    float4 acc = make_float4(0.f, 0.f, 0.f, 0.f);
#pragma unroll
    for (int e = 0; e < DEG; e++) {
        float a = s_alpha[g][hh][e];
        const uint2* hv = (const uint2*)(g_hh + (size_t)s_src[g][e] * HF);
        uint2 u = hv[t];                        // 4 halves
        float2 f0 = __half22float2(*reinterpret_cast<__half2*>(&u.x));
        float2 f1 = __half22float2(*reinterpret_cast<__half2*>(&u.y));
        acc.x += a * f0.x;  acc.y += a * f0.y;
        acc.z += a * f1.x;  acc.w += a * f1.y;
    }
    ((float4*)out)[node * (HF / 4) + t] = acc;
}

// ---------------------------------------------------------------------------
// Launch: inputs in metadata order:
//   0: x   1: row_id (unused)   2: row_ptr (unused)
//   3: col_id   4: W   5: att_i   6: att_j
// ---------------------------------------------------------------------------
extern "C" void kernel_launch(void* const* d_in, const int* in_sizes, int n_in,
                              void* d_out, int out_size)
{
    const float* x     = (const float*)d_in[0];
    const int*   col   = (const int*)  d_in[3];
    const float* W     = (const float*)d_in[4];
    const float* att_i = (const float*)d_in[5];
    const float* att_j = (const float*)d_in[6];
    float*       out   = (float*)d_out;

    cudaFuncSetAttribute(gemm_mma_kernel,
                         cudaFuncAttributeMaxDynamicSharedMemorySize,
                         GEMM_SMEM);

    convert_kernel<<<(XQ + WQ + 255) / 256, 256>>>(x, W);

    dim3 grid(2, NPAD / 256);              // (2, 196)
    gemm_mma_kernel<<<grid, GT, GEMM_SMEM>>>(att_i, att_j);

    gat_kernel<<<N_NODES / 4, 256>>>(col, out);
}

// round 7
// speedup vs baseline: 3.3445x; 1.0803x over previous
#include <cuda_runtime.h>
#include <cuda_fp16.h>
#include <cstdint>

// Problem constants (fixed by the reference setup)
#define N_NODES 50000
#define NPAD    50176        // padded to 128-row multiple
#define DEG     16
#define IN_F    256
#define HEADS   4
#define OUT_F   64
#define HF      256          // HEADS * OUT_F
#define NEG_SLOPE 0.2f

// Scratch (allocation-free rule: __device__ globals)
__device__ __half g_hh[N_NODES * HF];      // projected features, fp16, 25.6 MB
__device__ float g_ai[N_NODES * HEADS];
__device__ float g_aj[N_NODES * HEADS];
__device__ __half g_xh[NPAD * IN_F];       // x in fp16, 25.7 MB
__device__ __half g_wh[HF * IN_F];         // W in fp16, 128 KB

// ===========================================================================
// helpers
// ===========================================================================
__device__ __forceinline__ uint32_t smem_to_u32(const void* p) {
    uint32_t a;
    asm("{ .reg .u64 t; cvta.to.shared.u64 t, %1; cvt.u32.u64 %0, t; }"
        : "=r"(a) : "l"(p));
    return a;
}
__device__ __forceinline__ void ldsm4(uint32_t* r, uint32_t addr) {
    asm volatile("ldmatrix.sync.aligned.m8n8.x4.shared.b16 {%0,%1,%2,%3}, [%4];"
                 : "=r"(r[0]), "=r"(r[1]), "=r"(r[2]), "=r"(r[3]) : "r"(addr));
}
__device__ __forceinline__ void mma_f16(float* d, const uint32_t* a,
                                        uint32_t b0, uint32_t b1) {
    asm volatile("mma.sync.aligned.m16n8k16.row.col.f32.f16.f16.f32 "
                 "{%0,%1,%2,%3}, {%4,%5,%6,%7}, {%8,%9}, {%0,%1,%2,%3};"
                 : "+f"(d[0]), "+f"(d[1]), "+f"(d[2]), "+f"(d[3])
                 : "r"(a[0]), "r"(a[1]), "r"(a[2]), "r"(a[3]), "r"(b0), "r"(b1));
}
__device__ __forceinline__ void cp16(uint32_t dst, const void* src) {
    asm volatile("cp.async.cg.shared.global [%0], [%1], 16;"
                 :: "r"(dst), "l"(src));
}
#define CP_COMMIT() asm volatile("cp.async.commit_group;")
#define CP_WAIT(n)  asm volatile("cp.async.wait_group %0;" :: "n"(n))

// ===========================================================================
// Kernel 0: one-shot fp16 conversion of x (padded+zero-filled) and W
// ===========================================================================
#define XQ (NPAD * IN_F / 4)
#define WQ (HF * IN_F / 4)
__global__ void __launch_bounds__(256)
convert_kernel(const float* __restrict__ x, const float* __restrict__ W)
{
    int idx = blockIdx.x * 256 + threadIdx.x;
    if (idx < XQ) {
        int row = idx >> 6;
        float4 v = (row < N_NODES)
                 ? reinterpret_cast<const float4*>(x)[idx]
                 : make_float4(0.f, 0.f, 0.f, 0.f);
        uint2 o;
        __half2 p0 = __floats2half2_rn(v.x, v.y);
        __half2 p1 = __floats2half2_rn(v.z, v.w);
        o.x = *reinterpret_cast<uint32_t*>(&p0);
        o.y = *reinterpret_cast<uint32_t*>(&p1);
        reinterpret_cast<uint2*>(g_xh)[idx] = o;
    } else if (idx - XQ < WQ) {
        int w = idx - XQ;
        float4 v = reinterpret_cast<const float4*>(W)[w];
        uint2 o;
        __half2 p0 = __floats2half2_rn(v.x, v.y);
        __half2 p1 = __floats2half2_rn(v.z, v.w);
        o.x = *reinterpret_cast<uint32_t*>(&p0);
        o.y = *reinterpret_cast<uint32_t*>(&p1);
        reinterpret_cast<uint2*>(g_wh)[w] = o;
    }
}

// ===========================================================================
// Kernel 1: cp.async double-buffered fp16 GEMM, 2 CTAs/SM
// g_hh = x @ W^T (M=50176, N=256, K=256), fp32 accum.
// CTA tile 128x128 (grid 2 x 392), 8 warps (4M x 2N), warp tile 32x64,
// K staged by 64, 2-deep SMEM pipeline. Fused g_ai/g_aj epilogue (fp32).
// ===========================================================================
#define GT        256
#define STRB      144                     // smem row stride in bytes (64+8 fp16)
#define TILE_A    (128 * STRB)            // 18432 B
#define TILE_W    (128 * STRB)            // 18432 B
#define OFF_A     0
#define OFF_B     (TILE_A)
#define BUF_B     (TILE_A + TILE_W)       // 36864 B per stage
#define GEMM_SMEM (2 * BUF_B)             // 73728 B  (x2 CTAs = 147KB/SM)

extern __shared__ char g_smem[];

__global__ void __launch_bounds__(GT, 2)
gemm_mma_kernel(const float* __restrict__ att_i, const float* __restrict__ att_j)
{
    const int tid  = threadIdx.x;
    const int wid  = tid >> 5;
    const int lane = tid & 31;
    const int wm   = wid >> 1;            // 0..3 (M dim)
    const int wn   = wid & 1;             // 0..1 (N dim)
    const int bx   = blockIdx.x;          // N block (0,1)
    const int m0   = blockIdx.y * 128;

    const uint32_t sb = smem_to_u32(g_smem);

    const char* xh = reinterpret_cast<const char*>(g_xh);
    const char* wh = reinterpret_cast<const char*>(g_wh);

#define STAGE_LOAD(s, buf)                                                     \
    do {                                                                       \
        const int _k0b = (s) * 128;  /* 64 fp16 = 128 bytes */                 \
        const uint32_t _d0 = sb + (buf) * BUF_B;                               \
        _Pragma("unroll")                                                      \
        for (int _c = tid; _c < 1024; _c += GT) {     /* A: 128 rows x 8 */    \
            int _row = _c >> 3, _col = (_c & 7) * 16;                          \
            uint32_t _d = _d0 + (uint32_t)_row * STRB + _col;                  \
            size_t _ao = (size_t)(m0 + _row) * 512 + _k0b + _col;              \
            cp16(_d + OFF_A, xh + _ao);                                        \
        }                                                                      \
        _Pragma("unroll")                                                      \
        for (int _c = tid; _c < 1024; _c += GT) {     /* B: 128 rows x 8 */    \
            int _row = _c >> 3, _col = (_c & 7) * 16;                          \
            uint32_t _d = _d0 + (uint32_t)_row * STRB + _col;                  \
            size_t _bo = (size_t)(bx * 128 + _row) * 512 + _k0b + _col;        \
            cp16(_d + OFF_B, wh + _bo);                                        \
        }                                                                      \
        CP_COMMIT();                                                           \
    } while (0)

    float acc[2][8][4] = {};

    STAGE_LOAD(0, 0);

    for (int s = 0; s < 4; s++) {
        const int buf = s & 1;
        if (s < 3) {
            STAGE_LOAD(s + 1, buf ^ 1);
            CP_WAIT(1);
        } else {
            CP_WAIT(0);
        }
        __syncthreads();

        const uint32_t bbuf = sb + buf * BUF_B;
        const uint32_t aB = bbuf + OFF_A, bB = bbuf + OFF_B;

#pragma unroll
        for (int ks = 0; ks < 4; ks++) {
            const uint32_t kb = (uint32_t)ks * 32;

            uint32_t aoff = (uint32_t)(wm * 32 + (lane & 15)) * STRB
                          + kb + ((lane >> 4) << 4);
            uint32_t A0[4], A1[4];
            ldsm4(A0, aB + aoff);
            ldsm4(A1, aB + aoff + 16 * STRB);

            uint32_t nrow = (uint32_t)(wn * 64) + (lane & 7) + ((lane >> 4) << 3);
            uint32_t khalf = (lane >> 3) & 1;
            uint32_t bbase = nrow * STRB + kb + khalf * 16;
#pragma unroll
            for (int p = 0; p < 4; p++) {
                uint32_t Bf[4];
                ldsm4(Bf, bB + bbase + (uint32_t)p * 16 * STRB);
#pragma unroll
                for (int h = 0; h < 2; h++) {
                    const int nt = p * 2 + h;
                    mma_f16(acc[0][nt], A0, Bf[h * 2], Bf[h * 2 + 1]);
                    mma_f16(acc[1][nt], A1, Bf[h * 2], Bf[h * 2 + 1]);
                }
            }
        }
        __syncthreads();
    }

    // ---- epilogue: write g_hh (fp16) + fused attention dots (fp32) ----
    const int head    = bx * 2 + wn;
    const int colbase = bx * 128 + wn * 64;
    const int rbase   = m0 + wm * 32 + (lane >> 2);
    float si[2][2] = {}, sj[2][2] = {};

#pragma unroll
    for (int nt = 0; nt < 8; nt++) {
        const int g = colbase + nt * 8 + (lane & 3) * 2;
        const float ai0 = att_i[g], ai1 = att_i[g + 1];
        const float aj0 = att_j[g], aj1 = att_j[g + 1];
#pragma unroll
        for (int mt = 0; mt < 2; mt++) {
            si[mt][0] += acc[mt][nt][0] * ai0 + acc[mt][nt][1] * ai1;
            sj[mt][0] += acc[mt][nt][0] * aj0 + acc[mt][nt][1] * aj1;
            si[mt][1] += acc[mt][nt][2] * ai0 + acc[mt][nt][3] * ai1;
            sj[mt][1] += acc[mt][nt][2] * aj0 + acc[mt][nt][3] * aj1;
            const int r0 = rbase + mt * 16;
            if (r0 < N_NODES)
                *reinterpret_cast<__half2*>(g_hh + (size_t)r0 * HF + g)
                    = __floats2half2_rn(acc[mt][nt][0], acc[mt][nt][1]);
            const int r1 = r0 + 8;
            if (r1 < N_NODES)
                *reinterpret_cast<__half2*>(g_hh + (size_t)r1 * HF + g)
                    = __floats2half2_rn(acc[mt][nt][2], acc[mt][nt][3]);
        }
    }
#pragma unroll
    for (int off = 1; off <= 2; off <<= 1) {
#pragma unroll
        for (int mt = 0; mt < 2; mt++)
#pragma unroll
            for (int hf = 0; hf < 2; hf++) {
                si[mt][hf] += __shfl_xor_sync(0xffffffffu, si[mt][hf], off);
                sj[mt][hf] += __shfl_xor_sync(0xffffffffu, sj[mt][hf], off);
            }
    }
    if ((lane & 3) == 0) {
#pragma unroll
        for (int mt = 0; mt < 2; mt++)
#pragma unroll
            for (int hf = 0; hf < 2; hf++) {
                const int r = rbase + mt * 16 + hf * 8;
                if (r < N_NODES) {
                    g_ai[(size_t)r * HEADS + head] = si[mt][hf];
                    g_aj[(size_t)r * HEADS + head] = sj[mt][hf];
                }
            }
    }
}

// ---------------------------------------------------------------------------
// Kernel 2: warp-per-node GAT aggregate, barrier-free.
// Lanes 0-15 hold edges (dup in 16-31); logits for 2 heads per lane (float2),
// butterfly softmax over 16-lane groups; each lane then gathers 16B/row
// (8 halves) per edge with per-edge alpha fetched via shfl.
// ---------------------------------------------------------------------------
__global__ void __launch_bounds__(256) gat_kernel(const int* __restrict__ col32,
                                                  float* __restrict__ out)
{
    const int lane = threadIdx.x & 31;
    const int node = blockIdx.x * 8 + (threadIdx.x >> 5);

    const int is64 = ((col32[1] | col32[3] | col32[5]) == 0);

    // ---- edge source ids (lanes 0-15; duplicated in 16-31) ----
    const int e_ln = lane & 15;
    const int eg   = node * DEG + e_ln;
    const int src  = is64 ? col32[2 * eg] : col32[eg];

    // ---- logits for heads [half*2, half*2+1] of edge e_ln ----
    const int half = lane >> 4;
    float2 ai = *reinterpret_cast<const float2*>(g_ai + node * HEADS + half * 2);
    float2 aj = *reinterpret_cast<const float2*>(g_aj + (size_t)src * HEADS + half * 2);
    float lx = ai.x + aj.x;  lx = (lx > 0.f) ? lx : lx * NEG_SLOPE;
    float ly = ai.y + aj.y;  ly = (ly > 0.f) ? ly : ly * NEG_SLOPE;

    // ---- softmax over the 16 edges (within each 16-lane group) ----
    float mx = lx, my = ly;
#pragma unroll
    for (int off = 1; off < 16; off <<= 1) {
        mx = fmaxf(mx, __shfl_xor_sync(0xffffffffu, mx, off));
        my = fmaxf(my, __shfl_xor_sync(0xffffffffu, my, off));
    }
    float px = __expf(lx - mx), py = __expf(ly - my);
    // use exact expf for reference-level accuracy
    px = expf(lx - mx);  py = expf(ly - my);
    float sx = px, sy = py;
#pragma unroll
    for (int off = 1; off < 16; off <<= 1) {
        sx += __shfl_xor_sync(0xffffffffu, sx, off);
        sy += __shfl_xor_sync(0xffffffffu, sy, off);
    }
    float ax = px / (sx + 1e-16f);
    float ay = py / (sy + 1e-16f);

    // ---- distribute alpha + src per edge to all lanes ----
    const int hh = lane >> 3;               // head owned by this lane's features
    const int slgrp = (hh & 2) << 3;        // 0 or 16: lane group holding this head pair
    float aE[DEG];
    int   sE[DEG];
#pragma unroll
    for (int e = 0; e < DEG; e++) {
        sE[e] = __shfl_sync(0xffffffffu, src, e);
        float vx = __shfl_sync(0xffffffffu, ax, slgrp + e);
        float vy = __shfl_sync(0xffffffffu, ay, slgrp + e);
        aE[e] = (hh & 1) ? vy : vx;
    }

    // ---- gather + weighted sum: lane owns halves [lane*8, lane*8+8) ----
    float acc[8] = {};
#pragma unroll
    for (int e = 0; e < DEG; e++) {
        const uint4* rp = reinterpret_cast<const uint4*>(g_hh + (size_t)sE[e] * HF);
        uint4 v = rp[lane];
        float a = aE[e];
        float2 f0 = __half22float2(*reinterpret_cast<__half2*>(&v.x));
        float2 f1 = __half22float2(*reinterpret_cast<__half2*>(&v.y));
        float2 f2 = __half22float2(*reinterpret_cast<__half2*>(&v.z));
        float2 f3 = __half22float2(*reinterpret_cast<__half2*>(&v.w));
        acc[0] += a * f0.x;  acc[1] += a * f0.y;
        acc[2] += a * f1.x;  acc[3] += a * f1.y;
        acc[4] += a * f2.x;  acc[5] += a * f2.y;
        acc[6] += a * f3.x;  acc[7] += a * f3.y;
    }

    float4* op = reinterpret_cast<float4*>(out + (size_t)node * HF + lane * 8);
    op[0] = make_float4(acc[0], acc[1], acc[2], acc[3]);
    op[1] = make_float4(acc[4], acc[5], acc[6], acc[7]);
}

// ---------------------------------------------------------------------------
// Launch: inputs in metadata order:
//   0: x   1: row_id (unused)   2: row_ptr (unused)
//   3: col_id   4: W   5: att_i   6: att_j
// ---------------------------------------------------------------------------
extern "C" void kernel_launch(void* const* d_in, const int* in_sizes, int n_in,
                              void* d_out, int out_size)
{
    const float* x     = (const float*)d_in[0];
    const int*   col   = (const int*)  d_in[3];
    const float* W     = (const float*)d_in[4];
    const float* att_i = (const float*)d_in[5];
    const float* att_j = (const float*)d_in[6];
    float*       out   = (float*)d_out;

    cudaFuncSetAttribute(gemm_mma_kernel,
                         cudaFuncAttributeMaxDynamicSharedMemorySize,
                         GEMM_SMEM);

    convert_kernel<<<(XQ + WQ + 255) / 256, 256>>>(x, W);

    dim3 grid(2, NPAD / 128);              // (2, 392)
    gemm_mma_kernel<<<grid, GT, GEMM_SMEM>>>(att_i, att_j);

    gat_kernel<<<N_NODES / 8, 256>>>(col, out);
}

// round 8
// speedup vs baseline: 3.7328x; 1.1161x over previous
#include <cuda_runtime.h>
#include <cuda_fp16.h>
#include <cstdint>

// Problem constants (fixed by the reference setup)
#define N_NODES 50000
#define NPAD    50176        // padded to 128-row multiple
#define DEG     16
#define IN_F    256
#define HEADS   4
#define OUT_F   64
#define HF      256          // HEADS * OUT_F
#define NEG_SLOPE 0.2f

// Scratch (allocation-free rule: __device__ globals)
__device__ __half g_hh[N_NODES * HF];      // projected features, fp16, 25.6 MB
__device__ float g_ai[N_NODES * HEADS];
__device__ float g_aj[N_NODES * HEADS];
__device__ __half g_wh[HF * IN_F];         // W in fp16, 128 KB

// ===========================================================================
// helpers
// ===========================================================================
__device__ __forceinline__ uint32_t smem_to_u32(const void* p) {
    uint32_t a;
    asm("{ .reg .u64 t; cvta.to.shared.u64 t, %1; cvt.u32.u64 %0, t; }"
        : "=r"(a) : "l"(p));
    return a;
}
__device__ __forceinline__ void ldsm4(uint32_t* r, uint32_t addr) {
    asm volatile("ldmatrix.sync.aligned.m8n8.x4.shared.b16 {%0,%1,%2,%3}, [%4];"
                 : "=r"(r[0]), "=r"(r[1]), "=r"(r[2]), "=r"(r[3]) : "r"(addr));
}
__device__ __forceinline__ void mma_f16(float* d, const uint32_t* a,
                                        uint32_t b0, uint32_t b1) {
    asm volatile("mma.sync.aligned.m16n8k16.row.col.f32.f16.f16.f32 "
                 "{%0,%1,%2,%3}, {%4,%5,%6,%7}, {%8,%9}, {%0,%1,%2,%3};"
                 : "+f"(d[0]), "+f"(d[1]), "+f"(d[2]), "+f"(d[3])
                 : "r"(a[0]), "r"(a[1]), "r"(a[2]), "r"(a[3]), "r"(b0), "r"(b1));
}
__device__ __forceinline__ void cp16(uint32_t dst, const void* src) {
    asm volatile("cp.async.cg.shared.global [%0], [%1], 16;"
                 :: "r"(dst), "l"(src));
}
// cp.async with source-size (0 => zero-fill)
__device__ __forceinline__ void cp16z(uint32_t dst, const void* src, int srcsz) {
    asm volatile("cp.async.cg.shared.global [%0], [%1], 16, %2;"
                 :: "r"(dst), "l"(src), "r"(srcsz));
}
#define CP_COMMIT() asm volatile("cp.async.commit_group;")
#define CP_WAIT(n)  asm volatile("cp.async.wait_group %0;" :: "n"(n))

// ===========================================================================
// Kernel 0: one-shot fp16 conversion of W only (x converts inside the GEMM)
// ===========================================================================
#define WQ (HF * IN_F / 4)
__global__ void __launch_bounds__(256)
convert_w_kernel(const float* __restrict__ W)
{
    int idx = blockIdx.x * 256 + threadIdx.x;
    if (idx < WQ) {
        float4 v = reinterpret_cast<const float4*>(W)[idx];
        uint2 o;
        __half2 p0 = __floats2half2_rn(v.x, v.y);
        __half2 p1 = __floats2half2_rn(v.z, v.w);
        o.x = *reinterpret_cast<uint32_t*>(&p0);
        o.y = *reinterpret_cast<uint32_t*>(&p1);
        reinterpret_cast<uint2*>(g_wh)[idx] = o;
    }
}

// ===========================================================================
// Kernel 1: fp16 GEMM with fused in-kernel x conversion, 2 CTAs/SM.
// g_hh = x @ W^T (M=50176, N=256, K=256), fp32 accum.
// CTA tile 128x128 (grid 2 x 392), 8 warps (4M x 2N), warp tile 32x64.
// A path: cp.async f32 -> SMEM (single buf) -> convert pass -> fp16 double buf.
// B path: cp.async fp16 double buffered. Fused g_ai/g_aj epilogue.
// ===========================================================================
#define GT        256
#define STRB      144                     // fp16 tile row stride bytes (64+8)
#define OFF_AF32  0                       // 128 rows x 256B = 32768 B
#define AF32_B    32768
#define OFF_A16   (AF32_B)                // 2 x 18432 B
#define T16_B     (128 * STRB)            // 18432
#define OFF_B16   (AF32_B + 2 * T16_B)    // 2 x 18432 B
#define GEMM_SMEM (AF32_B + 4 * T16_B)    // 106496 B (x2 CTAs = 208 KB/SM)

extern __shared__ char g_smem[];

__global__ void __launch_bounds__(GT, 2)
gemm_mma_kernel(const float* __restrict__ x,
                const float* __restrict__ att_i, const float* __restrict__ att_j)
{
    const int tid  = threadIdx.x;
    const int wid  = tid >> 5;
    const int lane = tid & 31;
    const int wm   = wid >> 1;            // 0..3 (M dim)
    const int wn   = wid & 1;             // 0..1 (N dim)
    const int bx   = blockIdx.x;          // N block (0,1)
    const int m0   = blockIdx.y * 128;

    const uint32_t sb = smem_to_u32(g_smem);
    const char* xb = reinterpret_cast<const char*>(x);
    const char* wh = reinterpret_cast<const char*>(g_wh);

    // ---- stage issue: A f32 (2048 chunks) + B fp16 (1024 chunks) ----
#define STAGE_ISSUE(s, buf)                                                    \
    do {                                                                       \
        _Pragma("unroll")                                                      \
        for (int _c = tid; _c < 2048; _c += GT) {   /* A: 128 rows x 16 */     \
            int _row = _c >> 4, _col = (_c & 15) * 16;                         \
            int _gr = m0 + _row;                                               \
            int _ok = (_gr < N_NODES) ? 16 : 0;                                \
            size_t _ao = (size_t)(_ok ? _gr : 0) * 1024 + (s) * 256 + _col;    \
            cp16z(sb + OFF_AF32 + (uint32_t)_row * 256 + _col, xb + _ao, _ok); \
        }                                                                      \
        _Pragma("unroll")                                                      \
        for (int _c = tid; _c < 1024; _c += GT) {   /* B: 128 rows x 8 */      \
            int _row = _c >> 3, _col = (_c & 7) * 16;                          \
            size_t _bo = (size_t)(bx * 128 + _row) * 512 + (s) * 128 + _col;   \
            cp16(sb + OFF_B16 + (buf) * T16_B + (uint32_t)_row * STRB + _col,  \
                 wh + _bo);                                                    \
        }                                                                      \
        CP_COMMIT();                                                           \
    } while (0)

    float acc[2][8][4] = {};

    STAGE_ISSUE(0, 0);

    for (int s = 0; s < 4; s++) {
        const int buf = s & 1;

        CP_WAIT(0);
        __syncthreads();

        // ---- convert pass: A f32 SMEM -> fp16 tile buf ----
        {
            const uint32_t a16 = sb + OFF_A16 + buf * T16_B;
#pragma unroll
            for (int c = tid; c < 2048; c += GT) {      // 2048 float4
                int row = c >> 4, c4 = (c & 15) * 4;
                float4 v = *reinterpret_cast<const float4*>(
                    g_smem + OFF_AF32 + row * 256 + c4 * 4);
                __half2 p0 = __floats2half2_rn(v.x, v.y);
                __half2 p1 = __floats2half2_rn(v.z, v.w);
                uint2 o;
                o.x = *reinterpret_cast<uint32_t*>(&p0);
                o.y = *reinterpret_cast<uint32_t*>(&p1);
                asm volatile("st.shared.v2.b32 [%0], {%1, %2};"
                             :: "r"(a16 + (uint32_t)row * STRB + c4 * 2),
                                "r"(o.x), "r"(o.y));
            }
        }
        __syncthreads();   // converts done before Af32 is overwritten

        if (s < 3) STAGE_ISSUE(s + 1, buf ^ 1);

        const uint32_t aB = sb + OFF_A16 + buf * T16_B;
        const uint32_t bB = sb + OFF_B16 + buf * T16_B;

#pragma unroll
        for (int ks = 0; ks < 4; ks++) {
            const uint32_t kb = (uint32_t)ks * 32;

            uint32_t aoff = (uint32_t)(wm * 32 + (lane & 15)) * STRB
                          + kb + ((lane >> 4) << 4);
            uint32_t A0[4], A1[4];
            ldsm4(A0, aB + aoff);
            ldsm4(A1, aB + aoff + 16 * STRB);

            uint32_t nrow = (uint32_t)(wn * 64) + (lane & 7) + ((lane >> 4) << 3);
            uint32_t khalf = (lane >> 3) & 1;
            uint32_t bbase = nrow * STRB + kb + khalf * 16;
#pragma unroll
            for (int p = 0; p < 4; p++) {
                uint32_t Bf[4];
                ldsm4(Bf, bB + bbase + (uint32_t)p * 16 * STRB);
#pragma unroll
                for (int h = 0; h < 2; h++) {
                    const int nt = p * 2 + h;
                    mma_f16(acc[0][nt], A0, Bf[h * 2], Bf[h * 2 + 1]);
                    mma_f16(acc[1][nt], A1, Bf[h * 2], Bf[h * 2 + 1]);
                }
            }
        }
        // no trailing sync: next iter's CP_WAIT+sync covers all hazards
    }

    // ---- epilogue: write g_hh (fp16) + fused attention dots (fp32) ----
    const int head    = bx * 2 + wn;
    const int colbase = bx * 128 + wn * 64;
    const int rbase   = m0 + wm * 32 + (lane >> 2);
    float si[2][2] = {}, sj[2][2] = {};

#pragma unroll
    for (int nt = 0; nt < 8; nt++) {
        const int g = colbase + nt * 8 + (lane & 3) * 2;
        const float ai0 = att_i[g], ai1 = att_i[g + 1];
        const float aj0 = att_j[g], aj1 = att_j[g + 1];
#pragma unroll
        for (int mt = 0; mt < 2; mt++) {
            si[mt][0] += acc[mt][nt][0] * ai0 + acc[mt][nt][1] * ai1;
            sj[mt][0] += acc[mt][nt][0] * aj0 + acc[mt][nt][1] * aj1;
            si[mt][1] += acc[mt][nt][2] * ai0 + acc[mt][nt][3] * ai1;
            sj[mt][1] += acc[mt][nt][2] * aj0 + acc[mt][nt][3] * aj1;
            const int r0 = rbase + mt * 16;
            if (r0 < N_NODES)
                *reinterpret_cast<__half2*>(g_hh + (size_t)r0 * HF + g)
                    = __floats2half2_rn(acc[mt][nt][0], acc[mt][nt][1]);
            const int r1 = r0 + 8;
            if (r1 < N_NODES)
                *reinterpret_cast<__half2*>(g_hh + (size_t)r1 * HF + g)
                    = __floats2half2_rn(acc[mt][nt][2], acc[mt][nt][3]);
        }
    }
#pragma unroll
    for (int off = 1; off <= 2; off <<= 1) {
#pragma unroll
        for (int mt = 0; mt < 2; mt++)
#pragma unroll
            for (int hf = 0; hf < 2; hf++) {
                si[mt][hf] += __shfl_xor_sync(0xffffffffu, si[mt][hf], off);
                sj[mt][hf] += __shfl_xor_sync(0xffffffffu, sj[mt][hf], off);
            }
    }
    if ((lane & 3) == 0) {
#pragma unroll
        for (int mt = 0; mt < 2; mt++)
#pragma unroll
            for (int hf = 0; hf < 2; hf++) {
                const int r = rbase + mt * 16 + hf * 8;
                if (r < N_NODES) {
                    g_ai[(size_t)r * HEADS + head] = si[mt][hf];
                    g_aj[(size_t)r * HEADS + head] = sj[mt][hf];
                }
            }
    }
}

// ---------------------------------------------------------------------------
// Kernel 2: warp-per-node GAT aggregate, barrier-free.
// ---------------------------------------------------------------------------
__global__ void __launch_bounds__(256) gat_kernel(const int* __restrict__ col32,
                                                  float* __restrict__ out)
{
    const int lane = threadIdx.x & 31;
    const int node = blockIdx.x * 8 + (threadIdx.x >> 5);

    const int is64 = ((col32[1] | col32[3] | col32[5]) == 0);

    // ---- edge source ids (lanes 0-15; duplicated in 16-31) ----
    const int e_ln = lane & 15;
    const int eg   = node * DEG + e_ln;
    const int src  = is64 ? col32[2 * eg] : col32[eg];

    // ---- logits for heads [half*2, half*2+1] of edge e_ln ----
    const int half = lane >> 4;
    float2 ai = *reinterpret_cast<const float2*>(g_ai + node * HEADS + half * 2);
    float2 aj = *reinterpret_cast<const float2*>(g_aj + (size_t)src * HEADS + half * 2);
    float lx = ai.x + aj.x;  lx = (lx > 0.f) ? lx : lx * NEG_SLOPE;
    float ly = ai.y + aj.y;  ly = (ly > 0.f) ? ly : ly * NEG_SLOPE;

    // ---- softmax over the 16 edges (within each 16-lane group) ----
    float mx = lx, my = ly;
#pragma unroll
    for (int off = 1; off < 16; off <<= 1) {
        mx = fmaxf(mx, __shfl_xor_sync(0xffffffffu, mx, off));
        my = fmaxf(my, __shfl_xor_sync(0xffffffffu, my, off));
    }
    float px = expf(lx - mx), py = expf(ly - my);
    float sx = px, sy = py;
#pragma unroll
    for (int off = 1; off < 16; off <<= 1) {
        sx += __shfl_xor_sync(0xffffffffu, sx, off);
        sy += __shfl_xor_sync(0xffffffffu, sy, off);
    }
    float ax = px / (sx + 1e-16f);
    float ay = py / (sy + 1e-16f);

    // ---- distribute alpha + src per edge to all lanes ----
    const int hh = lane >> 3;               // head owned by this lane's features
    const int slgrp = (hh & 2) << 3;        // lane group holding this head pair
    float aE[DEG];
    int   sE[DEG];
#pragma unroll
    for (int e = 0; e < DEG; e++) {
        sE[e] = __shfl_sync(0xffffffffu, src, e);
        float vx = __shfl_sync(0xffffffffu, ax, slgrp + e);
        float vy = __shfl_sync(0xffffffffu, ay, slgrp + e);
        aE[e] = (hh & 1) ? vy : vx;
    }

    // ---- gather + weighted sum: lane owns halves [lane*8, lane*8+8) ----
    float acc[8] = {};
#pragma unroll
    for (int e = 0; e < DEG; e++) {
        const uint4* rp = reinterpret_cast<const uint4*>(g_hh + (size_t)sE[e] * HF);
        uint4 v = rp[lane];
        float a = aE[e];
        float2 f0 = __half22float2(*reinterpret_cast<__half2*>(&v.x));
        float2 f1 = __half22float2(*reinterpret_cast<__half2*>(&v.y));
        float2 f2 = __half22float2(*reinterpret_cast<__half2*>(&v.z));
        float2 f3 = __half22float2(*reinterpret_cast<__half2*>(&v.w));
        acc[0] += a * f0.x;  acc[1] += a * f0.y;
        acc[2] += a * f1.x;  acc[3] += a * f1.y;
        acc[4] += a * f2.x;  acc[5] += a * f2.y;
        acc[6] += a * f3.x;  acc[7] += a * f3.y;
    }

    float4* op = reinterpret_cast<float4*>(out + (size_t)node * HF + lane * 8);
    op[0] = make_float4(acc[0], acc[1], acc[2], acc[3]);
    op[1] = make_float4(acc[4], acc[5], acc[6], acc[7]);
}

// ---------------------------------------------------------------------------
// Launch: inputs in metadata order:
//   0: x   1: row_id (unused)   2: row_ptr (unused)
//   3: col_id   4: W   5: att_i   6: att_j
// ---------------------------------------------------------------------------
extern "C" void kernel_launch(void* const* d_in, const int* in_sizes, int n_in,
                              void* d_out, int out_size)
{
    const float* x     = (const float*)d_in[0];
    const int*   col   = (const int*)  d_in[3];
    const float* W     = (const float*)d_in[4];
    const float* att_i = (const float*)d_in[5];
    const float* att_j = (const float*)d_in[6];
    float*       out   = (float*)d_out;

    cudaFuncSetAttribute(gemm_mma_kernel,
                         cudaFuncAttributeMaxDynamicSharedMemorySize,
                         GEMM_SMEM);

    convert_w_kernel<<<(WQ + 255) / 256, 256>>>(W);

    dim3 grid(2, NPAD / 128);              // (2, 392)
    gemm_mma_kernel<<<grid, GT, GEMM_SMEM>>>(x, att_i, att_j);

    gat_kernel<<<N_NODES / 8, 256>>>(col, out);
}